// round 1
// baseline (speedup 1.0000x reference)
#include <cuda_runtime.h>
#include <math.h>

#define N_TOK 16384
#define DM 1024
#define EM 8
#define HM 256

// ---------------- scratch (device globals; no dynamic allocation) ----------
__device__ float g_xhat[(size_t)N_TOK * DM];   // 64 MB, expert-gathered LN'd tokens
__device__ float g_h[(size_t)N_TOK * HM];      // 16 MB, GELU(h) activations
__device__ int   g_top1[N_TOK];
__device__ float g_mu[N_TOK];
__device__ float g_rstd[N_TOK];
__device__ int   g_perm[N_TOK];                // gathered row -> token id
__device__ int   g_counts[EM];
__device__ int   g_offsets[EM + 1];
__device__ int   g_cursor[EM];

// ---------------- 0: zero counters -----------------------------------------
__global__ void k_zero() {
    if (threadIdx.x < EM) g_counts[threadIdx.x] = 0;
}

// ---------------- 1: router + LN stats --------------------------------------
// one block (256 thr) per token
__global__ __launch_bounds__(256) void k_router(const float* __restrict__ x,
                                                const float* __restrict__ Wg) {
    const int n = blockIdx.x;
    const int t = threadIdx.x;
    const float* xr = x + (size_t)n * DM;

    float s = 0.f, ss = 0.f;
    float lg[EM];
#pragma unroll
    for (int e = 0; e < EM; e++) lg[e] = 0.f;

#pragma unroll
    for (int j = 0; j < 4; j++) {
        int i = t + 256 * j;
        float xv = xr[i];
        s += xv;
        ss += xv * xv;
#pragma unroll
        for (int e = 0; e < EM; e++) lg[e] += xv * Wg[e * DM + i];
    }

    // warp reduce
#pragma unroll
    for (int o = 16; o > 0; o >>= 1) {
        s  += __shfl_down_sync(0xffffffffu, s, o);
        ss += __shfl_down_sync(0xffffffffu, ss, o);
#pragma unroll
        for (int e = 0; e < EM; e++)
            lg[e] += __shfl_down_sync(0xffffffffu, lg[e], o);
    }

    __shared__ float red[8][10];
    int warp = t >> 5, lane = t & 31;
    if (lane == 0) {
        red[warp][0] = s;
        red[warp][1] = ss;
#pragma unroll
        for (int e = 0; e < EM; e++) red[warp][2 + e] = lg[e];
    }
    __syncthreads();

    if (t == 0) {
        float S = 0.f, SS = 0.f;
        float L[EM];
#pragma unroll
        for (int e = 0; e < EM; e++) L[e] = 0.f;
#pragma unroll
        for (int w = 0; w < 8; w++) {
            S  += red[w][0];
            SS += red[w][1];
#pragma unroll
            for (int e = 0; e < EM; e++) L[e] += red[w][2 + e];
        }
        float mu = S / (float)DM;
        float var = SS / (float)DM - mu * mu;
        float rstd = rsqrtf(var + 1e-5f);
        int best = 0;
        float bv = L[0];
#pragma unroll
        for (int e = 1; e < EM; e++) {
            if (L[e] > bv) { bv = L[e]; best = e; }   // first-max wins (== jnp.argmax)
        }
        g_top1[n] = best;
        g_mu[n] = mu;
        g_rstd[n] = rstd;
        atomicAdd(&g_counts[best], 1);
    }
}

// ---------------- 2: scan -----------------------------------------------------
__global__ void k_scan() {
    if (threadIdx.x == 0) {
        int o = 0;
        g_offsets[0] = 0;
#pragma unroll
        for (int e = 0; e < EM; e++) {
            g_cursor[e] = o;
            o += g_counts[e];
            g_offsets[e + 1] = o;
        }
    }
}

// ---------------- 3: scatter (LN affine, expert-gathered layout) --------------
__global__ __launch_bounds__(256) void k_scatter(const float* __restrict__ x,
                                                 const float* __restrict__ ls,
                                                 const float* __restrict__ lb) {
    const int n = blockIdx.x;
    const int t = threadIdx.x;
    __shared__ int sp, se;
    if (t == 0) {
        int e = g_top1[n];
        int pos = atomicAdd(&g_cursor[e], 1);
        g_perm[pos] = n;
        sp = pos;
        se = e;
    }
    __syncthreads();
    const int pos = sp, e = se;
    const float mu = g_mu[n], rs = g_rstd[n];
    const float* xr = x + (size_t)n * DM;
    const float* lsr = ls + (size_t)e * DM;
    const float* lbr = lb + (size_t)e * DM;
    float* dst = g_xhat + (size_t)pos * DM;
#pragma unroll
    for (int j = 0; j < 4; j++) {
        int i = t + 256 * j;
        float xh = (xr[i] - mu) * rs;
        dst[i] = xh * lsr[i] + lbr[i];
    }
}

// ---------------- tile -> (expert, tile_m) mapping -----------------------------
__device__ __forceinline__ bool map_tile(int bx, int& e_out, int& tm_out) {
    int acc = 0;
    int e = -1, tm = 0;
#pragma unroll
    for (int i = 0; i < EM; i++) {
        int cnt = g_offsets[i + 1] - g_offsets[i];
        int te = (cnt + 127) >> 7;
        if (e < 0 && bx < acc + te) { e = i; tm = bx - acc; }
        acc += te;
    }
    e_out = e;
    tm_out = tm;
    return e >= 0;
}

// ---------------- 4: GEMM1 (xhat @ W1 + b1, exact GELU) -> g_h ------------------
// 128x128 tile, BK=8, 256 threads, 8x8 per thread
__global__ __launch_bounds__(256) void k_gemm1(const float* __restrict__ W1,
                                               const float* __restrict__ b1) {
    __shared__ float As[8][132];
    __shared__ float Bs[8][132];

    int e, tm;
    if (!map_tile(blockIdx.x, e, tm)) return;
    const int row0 = g_offsets[e] + tm * 128;
    int rows = g_offsets[e + 1] - row0;
    if (rows > 128) rows = 128;
    const int col0 = blockIdx.y * 128;

    const float* B = W1 + (size_t)e * DM * HM;
    const int tid = threadIdx.x;
    const int tx = tid & 15, ty = tid >> 4;

    float c[8][8];
#pragma unroll
    for (int i = 0; i < 8; i++)
#pragma unroll
        for (int j = 0; j < 8; j++) c[i][j] = 0.f;

    for (int k0 = 0; k0 < DM; k0 += 8) {
#pragma unroll
        for (int i = 0; i < 4; i++) {
            int idx = tid + 256 * i;
            int kk = idx & 7, r = idx >> 3;
            float v = (r < rows) ? g_xhat[(size_t)(row0 + r) * DM + k0 + kk] : 0.f;
            As[kk][r] = v;
        }
#pragma unroll
        for (int i = 0; i < 4; i++) {
            int idx = tid + 256 * i;
            int kk = idx >> 7, cc = idx & 127;
            Bs[kk][cc] = B[(size_t)(k0 + kk) * HM + col0 + cc];
        }
        __syncthreads();
#pragma unroll
        for (int kk = 0; kk < 8; kk++) {
            float a[8], b[8];
#pragma unroll
            for (int i = 0; i < 8; i++) a[i] = As[kk][ty * 8 + i];
#pragma unroll
            for (int j = 0; j < 8; j++) b[j] = Bs[kk][tx * 8 + j];
#pragma unroll
            for (int i = 0; i < 8; i++)
#pragma unroll
                for (int j = 0; j < 8; j++) c[i][j] += a[i] * b[j];
        }
        __syncthreads();
    }

#pragma unroll
    for (int i = 0; i < 8; i++) {
        int r = ty * 8 + i;
        if (r < rows) {
            size_t orow = (size_t)(row0 + r) * HM;
#pragma unroll
            for (int j = 0; j < 8; j++) {
                int col = col0 + tx * 8 + j;
                float v = c[i][j] + b1[e * HM + col];
                v = 0.5f * v * (1.f + erff(v * 0.70710678118654752f));
                g_h[orow + col] = v;
            }
        }
    }
}

// ---------------- 5: GEMM2 (h @ W2 + b2) -> out (scattered) ---------------------
__global__ __launch_bounds__(256) void k_gemm2(const float* __restrict__ W2,
                                               const float* __restrict__ b2,
                                               float* __restrict__ out) {
    __shared__ float As[8][132];
    __shared__ float Bs[8][132];

    int e, tm;
    if (!map_tile(blockIdx.x, e, tm)) return;
    const int row0 = g_offsets[e] + tm * 128;
    int rows = g_offsets[e + 1] - row0;
    if (rows > 128) rows = 128;
    const int col0 = blockIdx.y * 128;

    const float* B = W2 + (size_t)e * HM * DM;
    const int tid = threadIdx.x;
    const int tx = tid & 15, ty = tid >> 4;

    float c[8][8];
#pragma unroll
    for (int i = 0; i < 8; i++)
#pragma unroll
        for (int j = 0; j < 8; j++) c[i][j] = 0.f;

    for (int k0 = 0; k0 < HM; k0 += 8) {
#pragma unroll
        for (int i = 0; i < 4; i++) {
            int idx = tid + 256 * i;
            int kk = idx & 7, r = idx >> 3;
            float v = (r < rows) ? g_h[(size_t)(row0 + r) * HM + k0 + kk] : 0.f;
            As[kk][r] = v;
        }
#pragma unroll
        for (int i = 0; i < 4; i++) {
            int idx = tid + 256 * i;
            int kk = idx >> 7, cc = idx & 127;
            Bs[kk][cc] = B[(size_t)(k0 + kk) * DM + col0 + cc];
        }
        __syncthreads();
#pragma unroll
        for (int kk = 0; kk < 8; kk++) {
            float a[8], b[8];
#pragma unroll
            for (int i = 0; i < 8; i++) a[i] = As[kk][ty * 8 + i];
#pragma unroll
            for (int j = 0; j < 8; j++) b[j] = Bs[kk][tx * 8 + j];
#pragma unroll
            for (int i = 0; i < 8; i++)
#pragma unroll
                for (int j = 0; j < 8; j++) c[i][j] += a[i] * b[j];
        }
        __syncthreads();
    }

#pragma unroll
    for (int i = 0; i < 8; i++) {
        int r = ty * 8 + i;
        if (r < rows) {
            int n = g_perm[row0 + r];
            float* orow = out + (size_t)n * DM;
#pragma unroll
            for (int j = 0; j < 8; j++) {
                int col = col0 + tx * 8 + j;
                orow[col] = c[i][j] + b2[e * DM + col];
            }
        }
    }
}

// ---------------- launch -------------------------------------------------------
extern "C" void kernel_launch(void* const* d_in, const int* in_sizes, int n_in,
                              void* d_out, int out_size) {
    (void)in_sizes; (void)n_in; (void)out_size;
    const float* x  = (const float*)d_in[0];
    const float* Wg = (const float*)d_in[1];
    const float* ls = (const float*)d_in[2];
    const float* lb = (const float*)d_in[3];
    const float* W1 = (const float*)d_in[4];
    const float* b1 = (const float*)d_in[5];
    const float* W2 = (const float*)d_in[6];
    const float* b2 = (const float*)d_in[7];
    float* out = (float*)d_out;

    const int MAX_TILES = (N_TOK / 128) + EM;  // 136

    k_zero<<<1, 32>>>();
    k_router<<<N_TOK, 256>>>(x, Wg);
    k_scan<<<1, 1>>>();
    k_scatter<<<N_TOK, 256>>>(x, ls, lb);
    k_gemm1<<<dim3(MAX_TILES, HM / 128), 256>>>(W1, b1);
    k_gemm2<<<dim3(MAX_TILES, DM / 128), 256>>>(W2, b2, out);
}

// round 2
// speedup vs baseline: 1.6597x; 1.6597x over previous
#include <cuda_runtime.h>
#include <math.h>
#include <stdint.h>

#define N_TOK 16384
#define DM 1024
#define EM 8
#define HM 256

// ---------------- scratch (device globals) ----------------------------------
__device__ float g_h[(size_t)N_TOK * HM];      // 16 MB, GELU(h), permuted rows
__device__ int   g_top1[N_TOK];
__device__ float g_mu[N_TOK];
__device__ float g_rstd[N_TOK];
__device__ int   g_perm[N_TOK];                // gathered row -> token id
__device__ int   g_counts[EM];
__device__ int   g_offsets[EM + 1];
__device__ int   g_cursor[EM];

// ---------------- helpers ----------------------------------------------------
__device__ __forceinline__ uint32_t f2tf(float f) {
    uint32_t u;
    asm("cvt.rna.tf32.f32 %0, %1;" : "=r"(u) : "f"(f));
    return u;
}

__device__ __forceinline__ void mma8(float* c, const uint32_t* a, const uint32_t* b) {
    asm volatile(
        "mma.sync.aligned.m16n8k8.row.col.f32.tf32.tf32.f32 "
        "{%0,%1,%2,%3},{%4,%5,%6,%7},{%8,%9},{%0,%1,%2,%3};"
        : "+f"(c[0]), "+f"(c[1]), "+f"(c[2]), "+f"(c[3])
        : "r"(a[0]), "r"(a[1]), "r"(a[2]), "r"(a[3]), "r"(b[0]), "r"(b[1]));
}

// ---------------- 0: zero counters -------------------------------------------
__global__ void k_zero() {
    if (threadIdx.x < EM) g_counts[threadIdx.x] = 0;
}

// ---------------- 1: router + LN stats (exact fp32) ---------------------------
__global__ __launch_bounds__(256) void k_router(const float* __restrict__ x,
                                                const float* __restrict__ Wg) {
    const int n = blockIdx.x;
    const int t = threadIdx.x;
    const float* xr = x + (size_t)n * DM;

    float s = 0.f, ss = 0.f;
    float lg[EM];
#pragma unroll
    for (int e = 0; e < EM; e++) lg[e] = 0.f;

#pragma unroll
    for (int j = 0; j < 4; j++) {
        int i = t + 256 * j;
        float xv = xr[i];
        s += xv;
        ss += xv * xv;
#pragma unroll
        for (int e = 0; e < EM; e++) lg[e] += xv * Wg[e * DM + i];
    }

#pragma unroll
    for (int o = 16; o > 0; o >>= 1) {
        s  += __shfl_down_sync(0xffffffffu, s, o);
        ss += __shfl_down_sync(0xffffffffu, ss, o);
#pragma unroll
        for (int e = 0; e < EM; e++)
            lg[e] += __shfl_down_sync(0xffffffffu, lg[e], o);
    }

    __shared__ float red[8][10];
    int warp = t >> 5, lane = t & 31;
    if (lane == 0) {
        red[warp][0] = s;
        red[warp][1] = ss;
#pragma unroll
        for (int e = 0; e < EM; e++) red[warp][2 + e] = lg[e];
    }
    __syncthreads();

    if (t == 0) {
        float S = 0.f, SS = 0.f;
        float L[EM];
#pragma unroll
        for (int e = 0; e < EM; e++) L[e] = 0.f;
#pragma unroll
        for (int w = 0; w < 8; w++) {
            S  += red[w][0];
            SS += red[w][1];
#pragma unroll
            for (int e = 0; e < EM; e++) L[e] += red[w][2 + e];
        }
        float mu = S / (float)DM;
        float var = SS / (float)DM - mu * mu;
        int best = 0;
        float bv = L[0];
#pragma unroll
        for (int e = 1; e < EM; e++) {
            if (L[e] > bv) { bv = L[e]; best = e; }
        }
        g_top1[n] = best;
        g_mu[n] = mu;
        g_rstd[n] = rsqrtf(var + 1e-5f);
        atomicAdd(&g_counts[best], 1);
    }
}

// ---------------- 2: scan ------------------------------------------------------
__global__ void k_scan() {
    if (threadIdx.x == 0) {
        int o = 0;
        g_offsets[0] = 0;
#pragma unroll
        for (int e = 0; e < EM; e++) {
            g_cursor[e] = o;
            o += g_counts[e];
            g_offsets[e + 1] = o;
        }
    }
}

// ---------------- 3: build permutation ----------------------------------------
__global__ void k_perm() {
    int n = blockIdx.x * 256 + threadIdx.x;
    if (n < N_TOK) {
        int e = g_top1[n];
        int pos = atomicAdd(&g_cursor[e], 1);
        g_perm[pos] = n;
    }
}

// ---------------- tile -> (expert, tile_m) -------------------------------------
__device__ __forceinline__ bool map_tile(int bx, int& e_out, int& tm_out) {
    int acc = 0;
    int e = -1, tm = 0;
#pragma unroll
    for (int i = 0; i < EM; i++) {
        int cnt = g_offsets[i + 1] - g_offsets[i];
        int te = (cnt + 127) >> 7;
        if (e < 0 && bx < acc + te) { e = i; tm = bx - acc; }
        acc += te;
    }
    e_out = e;
    tm_out = tm;
    return e >= 0;
}

#define BK  32
#define AST 136   // As[k][m] stride (m padded)
#define BST 132   // Bs[k][n] stride (n padded)

// ---------------- 4: GEMM1  (gather+LN+affine) @ W1 + b1, GELU -> g_h ----------
__global__ __launch_bounds__(256) void k_gemm1(const float* __restrict__ x,
                                               const float* __restrict__ ls,
                                               const float* __restrict__ lb,
                                               const float* __restrict__ W1,
                                               const float* __restrict__ b1) {
    __shared__ uint32_t As[BK][AST];
    __shared__ uint32_t Bs[BK][BST];

    int e, tm;
    if (!map_tile(blockIdx.x, e, tm)) return;
    const int row0 = g_offsets[e] + tm * 128;
    int rows = g_offsets[e + 1] - row0;
    if (rows > 128) rows = 128;
    const int col0 = blockIdx.y * 128;

    const int tid = threadIdx.x;
    const int arow = tid & 127;       // A row owned by this thread
    const int c4b  = tid >> 7;        // 0/1: even/odd float4 chunks of the row
    const int ar = (arow < rows) ? arow : (rows - 1);
    const int tok = g_perm[row0 + ar];
    const float* xr = x + (size_t)tok * DM;
    const float mu = g_mu[tok], rs = g_rstd[tok];
    const float* lsr = ls + (size_t)e * DM;
    const float* lbr = lb + (size_t)e * DM;
    const float* Bg = W1 + (size_t)e * DM * HM;

    const int w = tid >> 5, lane = tid & 31;
    const int wm = w >> 1, wn = w & 1;
    const int g = lane >> 2, t = lane & 3;

    float c[2][8][4];
#pragma unroll
    for (int i = 0; i < 2; i++)
#pragma unroll
        for (int j = 0; j < 8; j++)
#pragma unroll
            for (int q = 0; q < 4; q++) c[i][j][q] = 0.f;

    float4 xa[4];
    float4 bsta[4];

    auto fetchA = [&](int k0) {
#pragma unroll
        for (int j = 0; j < 4; j++) {
            int kk = 4 * (c4b + 2 * j);
            float4 v = *(const float4*)(xr + k0 + kk);
            v.x = (v.x - mu) * rs;
            v.y = (v.y - mu) * rs;
            v.z = (v.z - mu) * rs;
            v.w = (v.w - mu) * rs;
            xa[j] = v;
        }
    };
    auto fetchB = [&](int k0) {
#pragma unroll
        for (int i = 0; i < 4; i++) {
            int lin = tid + 256 * i;
            int kk = lin >> 5, cc = (lin & 31) * 4;
            bsta[i] = *(const float4*)(Bg + (size_t)(k0 + kk) * HM + col0 + cc);
        }
    };
    auto storeA = [&](int k0) {
#pragma unroll
        for (int j = 0; j < 4; j++) {
            int kk = 4 * (c4b + 2 * j);
            float4 s = *(const float4*)(lsr + k0 + kk);
            float4 bb = *(const float4*)(lbr + k0 + kk);
            As[kk + 0][arow] = f2tf(xa[j].x * s.x + bb.x);
            As[kk + 1][arow] = f2tf(xa[j].y * s.y + bb.y);
            As[kk + 2][arow] = f2tf(xa[j].z * s.z + bb.z);
            As[kk + 3][arow] = f2tf(xa[j].w * s.w + bb.w);
        }
    };
    auto storeB = [&]() {
#pragma unroll
        for (int i = 0; i < 4; i++) {
            int lin = tid + 256 * i;
            int kk = lin >> 5, cc = (lin & 31) * 4;
            uint4 u;
            u.x = f2tf(bsta[i].x);
            u.y = f2tf(bsta[i].y);
            u.z = f2tf(bsta[i].z);
            u.w = f2tf(bsta[i].w);
            *(uint4*)&Bs[kk][cc] = u;
        }
    };
    auto compute = [&]() {
#pragma unroll
        for (int ks = 0; ks < BK; ks += 8) {
            uint32_t a[2][4], b[8][2];
#pragma unroll
            for (int mt = 0; mt < 2; mt++) {
                int m = wm * 32 + mt * 16;
                a[mt][0] = As[ks + t][m + g];
                a[mt][1] = As[ks + t][m + g + 8];
                a[mt][2] = As[ks + t + 4][m + g];
                a[mt][3] = As[ks + t + 4][m + g + 8];
            }
#pragma unroll
            for (int nt = 0; nt < 8; nt++) {
                int n = wn * 64 + nt * 8 + g;
                b[nt][0] = Bs[ks + t][n];
                b[nt][1] = Bs[ks + t + 4][n];
            }
#pragma unroll
            for (int mt = 0; mt < 2; mt++)
#pragma unroll
                for (int nt = 0; nt < 8; nt++)
                    mma8(c[mt][nt], a[mt], b[nt]);
        }
    };

    fetchA(0); fetchB(0);
    storeA(0); storeB();
    __syncthreads();
    for (int k0 = 0; k0 < DM; k0 += BK) {
        int kn = k0 + BK;
        if (kn < DM) { fetchA(kn); fetchB(kn); }
        compute();
        __syncthreads();
        if (kn < DM) { storeA(kn); storeB(); __syncthreads(); }
    }

    // epilogue: bias + exact GELU, store to g_h (permuted layout)
#pragma unroll
    for (int mt = 0; mt < 2; mt++) {
        int rl0 = wm * 32 + mt * 16 + g;
#pragma unroll
        for (int half = 0; half < 2; half++) {
            int rl = rl0 + 8 * half;
            if (rl < rows) {
                size_t orow = (size_t)(row0 + rl) * HM;
#pragma unroll
                for (int nt = 0; nt < 8; nt++) {
                    int col = col0 + wn * 64 + nt * 8 + 2 * t;
                    float v0 = c[mt][nt][2 * half + 0] + __ldg(&b1[e * HM + col]);
                    float v1 = c[mt][nt][2 * half + 1] + __ldg(&b1[e * HM + col + 1]);
                    v0 = 0.5f * v0 * (1.f + erff(v0 * 0.70710678118654752f));
                    v1 = 0.5f * v1 * (1.f + erff(v1 * 0.70710678118654752f));
                    *(float2*)&g_h[orow + col] = make_float2(v0, v1);
                }
            }
        }
    }
}

// ---------------- 5: GEMM2  g_h @ W2 + b2 -> out (scatter by perm) --------------
__global__ __launch_bounds__(256) void k_gemm2(const float* __restrict__ W2,
                                               const float* __restrict__ b2,
                                               float* __restrict__ out) {
    __shared__ uint32_t As[BK][AST];
    __shared__ uint32_t Bs[BK][BST];

    int e, tm;
    if (!map_tile(blockIdx.x, e, tm)) return;
    const int row0 = g_offsets[e] + tm * 128;
    int rows = g_offsets[e + 1] - row0;
    if (rows > 128) rows = 128;
    const int col0 = blockIdx.y * 128;

    const int tid = threadIdx.x;
    const int arow = tid & 127;
    const int c4b  = tid >> 7;
    const int ar = (arow < rows) ? arow : (rows - 1);
    const float* hr = g_h + (size_t)(row0 + ar) * HM;
    const float* Bg = W2 + (size_t)e * HM * DM;

    const int w = tid >> 5, lane = tid & 31;
    const int wm = w >> 1, wn = w & 1;
    const int g = lane >> 2, t = lane & 3;

    float c[2][8][4];
#pragma unroll
    for (int i = 0; i < 2; i++)
#pragma unroll
        for (int j = 0; j < 8; j++)
#pragma unroll
            for (int q = 0; q < 4; q++) c[i][j][q] = 0.f;

    float4 xa[4];
    float4 bsta[4];

    auto fetchA = [&](int k0) {
#pragma unroll
        for (int j = 0; j < 4; j++) {
            int kk = 4 * (c4b + 2 * j);
            xa[j] = *(const float4*)(hr + k0 + kk);
        }
    };
    auto fetchB = [&](int k0) {
#pragma unroll
        for (int i = 0; i < 4; i++) {
            int lin = tid + 256 * i;
            int kk = lin >> 5, cc = (lin & 31) * 4;
            bsta[i] = *(const float4*)(Bg + (size_t)(k0 + kk) * DM + col0 + cc);
        }
    };
    auto storeA = [&]() {
#pragma unroll
        for (int j = 0; j < 4; j++) {
            int kk = 4 * (c4b + 2 * j);
            As[kk + 0][arow] = f2tf(xa[j].x);
            As[kk + 1][arow] = f2tf(xa[j].y);
            As[kk + 2][arow] = f2tf(xa[j].z);
            As[kk + 3][arow] = f2tf(xa[j].w);
        }
    };
    auto storeB = [&]() {
#pragma unroll
        for (int i = 0; i < 4; i++) {
            int lin = tid + 256 * i;
            int kk = lin >> 5, cc = (lin & 31) * 4;
            uint4 u;
            u.x = f2tf(bsta[i].x);
            u.y = f2tf(bsta[i].y);
            u.z = f2tf(bsta[i].z);
            u.w = f2tf(bsta[i].w);
            *(uint4*)&Bs[kk][cc] = u;
        }
    };
    auto compute = [&]() {
#pragma unroll
        for (int ks = 0; ks < BK; ks += 8) {
            uint32_t a[2][4], b[8][2];
#pragma unroll
            for (int mt = 0; mt < 2; mt++) {
                int m = wm * 32 + mt * 16;
                a[mt][0] = As[ks + t][m + g];
                a[mt][1] = As[ks + t][m + g + 8];
                a[mt][2] = As[ks + t + 4][m + g];
                a[mt][3] = As[ks + t + 4][m + g + 8];
            }
#pragma unroll
            for (int nt = 0; nt < 8; nt++) {
                int n = wn * 64 + nt * 8 + g;
                b[nt][0] = Bs[ks + t][n];
                b[nt][1] = Bs[ks + t + 4][n];
            }
#pragma unroll
            for (int mt = 0; mt < 2; mt++)
#pragma unroll
                for (int nt = 0; nt < 8; nt++)
                    mma8(c[mt][nt], a[mt], b[nt]);
        }
    };

    fetchA(0); fetchB(0);
    storeA(); storeB();
    __syncthreads();
    for (int k0 = 0; k0 < HM; k0 += BK) {
        int kn = k0 + BK;
        if (kn < HM) { fetchA(kn); fetchB(kn); }
        compute();
        __syncthreads();
        if (kn < HM) { storeA(); storeB(); __syncthreads(); }
    }

    // epilogue: bias add, scatter rows back to token order
#pragma unroll
    for (int mt = 0; mt < 2; mt++) {
        int rl0 = wm * 32 + mt * 16 + g;
#pragma unroll
        for (int half = 0; half < 2; half++) {
            int rl = rl0 + 8 * half;
            if (rl < rows) {
                int tok = g_perm[row0 + rl];
                float* orow = out + (size_t)tok * DM;
#pragma unroll
                for (int nt = 0; nt < 8; nt++) {
                    int col = col0 + wn * 64 + nt * 8 + 2 * t;
                    float v0 = c[mt][nt][2 * half + 0] + __ldg(&b2[e * DM + col]);
                    float v1 = c[mt][nt][2 * half + 1] + __ldg(&b2[e * DM + col + 1]);
                    *(float2*)&orow[col] = make_float2(v0, v1);
                }
            }
        }
    }
}

// ---------------- launch --------------------------------------------------------
extern "C" void kernel_launch(void* const* d_in, const int* in_sizes, int n_in,
                              void* d_out, int out_size) {
    (void)in_sizes; (void)n_in; (void)out_size;
    const float* x  = (const float*)d_in[0];
    const float* Wg = (const float*)d_in[1];
    const float* ls = (const float*)d_in[2];
    const float* lb = (const float*)d_in[3];
    const float* W1 = (const float*)d_in[4];
    const float* b1 = (const float*)d_in[5];
    const float* W2 = (const float*)d_in[6];
    const float* b2 = (const float*)d_in[7];
    float* out = (float*)d_out;

    const int MAX_TILES = (N_TOK / 128) + EM;  // 136

    k_zero<<<1, 32>>>();
    k_router<<<N_TOK, 256>>>(x, Wg);
    k_scan<<<1, 1>>>();
    k_perm<<<64, 256>>>();
    k_gemm1<<<dim3(MAX_TILES, HM / 128), 256>>>(x, ls, lb, W1, b1);
    k_gemm2<<<dim3(MAX_TILES, DM / 128), 256>>>(W2, b2, out);
}

// round 3
// speedup vs baseline: 3.0048x; 1.8105x over previous
#include <cuda_runtime.h>
#include <math.h>
#include <stdint.h>

#define N_TOK 16384
#define DM 1024
#define EM 8
#define HM 256

// ---------------- scratch (device globals) ----------------------------------
__device__ float g_xa[(size_t)N_TOK * DM];     // 64 MB, gathered LN'd tokens (tf32 bits)
__device__ float g_h[(size_t)N_TOK * HM];      // 16 MB, GELU(h) (tf32 bits), permuted
__device__ float g_w1t[(size_t)EM * DM * HM];  // 8 MB, W1 in tf32
__device__ float g_w2t[(size_t)EM * HM * DM];  // 8 MB, W2 in tf32
__device__ int   g_top1[N_TOK];
__device__ float g_mu[N_TOK];
__device__ float g_rstd[N_TOK];
__device__ int   g_perm[N_TOK];
__device__ int   g_counts[EM];
__device__ int   g_offsets[EM + 1];
__device__ int   g_cursor[EM];

// ---------------- helpers ----------------------------------------------------
__device__ __forceinline__ uint32_t f2tf(float f) {
    uint32_t u;
    asm("cvt.rna.tf32.f32 %0, %1;" : "=r"(u) : "f"(f));
    return u;
}

__device__ __forceinline__ void mma8(float* c, const uint32_t* a, const uint32_t* b) {
    asm volatile(
        "mma.sync.aligned.m16n8k8.row.col.f32.tf32.tf32.f32 "
        "{%0,%1,%2,%3},{%4,%5,%6,%7},{%8,%9},{%0,%1,%2,%3};"
        : "+f"(c[0]), "+f"(c[1]), "+f"(c[2]), "+f"(c[3])
        : "r"(a[0]), "r"(a[1]), "r"(a[2]), "r"(a[3]), "r"(b[0]), "r"(b[1]));
}

__device__ __forceinline__ void cpa16(uint32_t dst, const void* src) {
    asm volatile("cp.async.cg.shared.global [%0], [%1], 16;" ::"r"(dst), "l"(src));
}
__device__ __forceinline__ void cpa_commit() {
    asm volatile("cp.async.commit_group;");
}
__device__ __forceinline__ void cpa_wait1() {
    asm volatile("cp.async.wait_group 1;");
}
__device__ __forceinline__ void cpa_wait0() {
    asm volatile("cp.async.wait_group 0;");
}

// ---------------- 0: zero counters -------------------------------------------
__global__ void k_zero() {
    if (threadIdx.x < EM) g_counts[threadIdx.x] = 0;
}

// ---------------- 1: router (one warp per token) ------------------------------
__global__ __launch_bounds__(256) void k_router(const float* __restrict__ x,
                                                const float* __restrict__ Wg) {
    const int warp = threadIdx.x >> 5, lane = threadIdx.x & 31;
    const int n = blockIdx.x * 8 + warp;
    const float4* xr = (const float4*)(x + (size_t)n * DM);
    const float4* wg = (const float4*)Wg;

    float s = 0.f, ss = 0.f;
    float lg[EM];
#pragma unroll
    for (int e = 0; e < EM; e++) lg[e] = 0.f;

#pragma unroll
    for (int j = 0; j < 8; j++) {
        float4 v = xr[lane + 32 * j];
        s += v.x + v.y + v.z + v.w;
        ss += v.x * v.x + v.y * v.y + v.z * v.z + v.w * v.w;
#pragma unroll
        for (int e = 0; e < EM; e++) {
            float4 w = wg[e * 256 + lane + 32 * j];
            lg[e] += v.x * w.x + v.y * w.y + v.z * w.z + v.w * w.w;
        }
    }
#pragma unroll
    for (int o = 16; o > 0; o >>= 1) {
        s  += __shfl_xor_sync(0xffffffffu, s, o);
        ss += __shfl_xor_sync(0xffffffffu, ss, o);
#pragma unroll
        for (int e = 0; e < EM; e++)
            lg[e] += __shfl_xor_sync(0xffffffffu, lg[e], o);
    }
    if (lane == 0) {
        float mu = s / (float)DM;
        float var = ss / (float)DM - mu * mu;
        int best = 0;
        float bv = lg[0];
#pragma unroll
        for (int e = 1; e < EM; e++)
            if (lg[e] > bv) { bv = lg[e]; best = e; }
        g_top1[n] = best;
        g_mu[n] = mu;
        g_rstd[n] = rsqrtf(var + 1e-5f);
        atomicAdd(&g_counts[best], 1);
    }
}

// ---------------- 2: scan ------------------------------------------------------
__global__ void k_scan() {
    if (threadIdx.x == 0) {
        int o = 0;
        g_offsets[0] = 0;
#pragma unroll
        for (int e = 0; e < EM; e++) {
            g_cursor[e] = o;
            o += g_counts[e];
            g_offsets[e + 1] = o;
        }
    }
}

// ---------------- 3: weights -> tf32 -------------------------------------------
__global__ __launch_bounds__(256) void k_wconv(const float* __restrict__ W1,
                                               const float* __restrict__ W2) {
    const int HALF = EM * DM * HM / 4;   // 524288 float4 per weight tensor
    int id = blockIdx.x * 256 + threadIdx.x;
    const float4* src = (id < HALF) ? (const float4*)W1 : (const float4*)W2;
    float4* dst = (id < HALF) ? (float4*)g_w1t : (float4*)g_w2t;
    int i = (id < HALF) ? id : id - HALF;
    float4 v = src[i];
    float4 o;
    o.x = __uint_as_float(f2tf(v.x));
    o.y = __uint_as_float(f2tf(v.y));
    o.z = __uint_as_float(f2tf(v.z));
    o.w = __uint_as_float(f2tf(v.w));
    dst[i] = o;
}

// ---------------- 4: scatter (gather + LN affine, tf32) -------------------------
__global__ __launch_bounds__(256) void k_scatter(const float* __restrict__ x,
                                                 const float* __restrict__ ls,
                                                 const float* __restrict__ lb) {
    const int n = blockIdx.x;
    const int t = threadIdx.x;
    __shared__ int sp, se;
    if (t == 0) {
        int e = g_top1[n];
        int pos = atomicAdd(&g_cursor[e], 1);
        g_perm[pos] = n;
        sp = pos;
        se = e;
    }
    __syncthreads();
    const int pos = sp, e = se;
    const float mu = g_mu[n], rs = g_rstd[n];
    float4 xv = ((const float4*)(x + (size_t)n * DM))[t];
    float4 sv = ((const float4*)(ls + (size_t)e * DM))[t];
    float4 bv = ((const float4*)(lb + (size_t)e * DM))[t];
    float4 o;
    o.x = __uint_as_float(f2tf((xv.x - mu) * rs * sv.x + bv.x));
    o.y = __uint_as_float(f2tf((xv.y - mu) * rs * sv.y + bv.y));
    o.z = __uint_as_float(f2tf((xv.z - mu) * rs * sv.z + bv.z));
    o.w = __uint_as_float(f2tf((xv.w - mu) * rs * sv.w + bv.w));
    ((float4*)(g_xa + (size_t)pos * DM))[t] = o;
}

// ---------------- tile -> (expert, tile_m) --------------------------------------
__device__ __forceinline__ bool map_tile(int bx, int& e_out, int& tm_out) {
    int acc = 0;
    int e = -1, tm = 0;
#pragma unroll
    for (int i = 0; i < EM; i++) {
        int cnt = g_offsets[i + 1] - g_offsets[i];
        int te = (cnt + 127) >> 7;
        if (e < 0 && bx < acc + te) { e = i; tm = bx - acc; }
        acc += te;
    }
    e_out = e;
    tm_out = tm;
    return e >= 0;
}

// ---------------- GEMM machinery -------------------------------------------------
#define BK 32
#define AS_STR 36          // As[m][k] word stride  (36 % 32 == 4  -> bank = 4g+t, distinct)
#define BS_STR 136         // Bs[k][n] word stride  (136 % 32 == 8 -> bank = 8t+g, distinct)
#define A_STAGE (128 * AS_STR)
#define B_STAGE (BK * BS_STR)
#define NSTG 3
#define SMEM_WORDS (NSTG * (A_STAGE + B_STAGE))
#define SMEM_BYTES (SMEM_WORDS * 4)

__device__ __forceinline__ void load_stage(uint32_t smem_u32, int stg,
                                           const float* Ag, int ldA, int row0,
                                           int rows, const float* Bg, int ldB,
                                           int col0, int k0, int tid) {
    uint32_t as_b = smem_u32 + (uint32_t)stg * (A_STAGE * 4);
    uint32_t bs_b = smem_u32 + (uint32_t)(NSTG * A_STAGE + stg * B_STAGE) * 4;
#pragma unroll
    for (int i = 0; i < 4; i++) {
        int id = tid + 256 * i;
        int r = id >> 3, kc = (id & 7) * 4;
        int rr = (r < rows) ? r : rows - 1;
        cpa16(as_b + (uint32_t)(r * AS_STR + kc) * 4,
              Ag + (size_t)(row0 + rr) * ldA + k0 + kc);
    }
#pragma unroll
    for (int i = 0; i < 4; i++) {
        int id = tid + 256 * i;
        int kr = id >> 5, nc = (id & 31) * 4;
        cpa16(bs_b + (uint32_t)(kr * BS_STR + nc) * 4,
              Bg + (size_t)(k0 + kr) * ldB + col0 + nc);
    }
}

__device__ __forceinline__ void compute_stage(const uint32_t* smem, int stg,
                                              int wm, int wn, int g, int t,
                                              float c[2][8][4]) {
    const uint32_t* As = smem + stg * A_STAGE;
    const uint32_t* Bs = smem + NSTG * A_STAGE + stg * B_STAGE;
#pragma unroll
    for (int ks = 0; ks < BK; ks += 8) {
        uint32_t a[2][4], b[8][2];
#pragma unroll
        for (int mt = 0; mt < 2; mt++) {
            int m = wm * 32 + mt * 16 + g;
            a[mt][0] = As[m * AS_STR + ks + t];
            a[mt][1] = As[(m + 8) * AS_STR + ks + t];
            a[mt][2] = As[m * AS_STR + ks + t + 4];
            a[mt][3] = As[(m + 8) * AS_STR + ks + t + 4];
        }
#pragma unroll
        for (int nt = 0; nt < 8; nt++) {
            int n = wn * 64 + nt * 8 + g;
            b[nt][0] = Bs[(ks + t) * BS_STR + n];
            b[nt][1] = Bs[(ks + t + 4) * BS_STR + n];
        }
#pragma unroll
        for (int mt = 0; mt < 2; mt++)
#pragma unroll
            for (int nt = 0; nt < 8; nt++)
                mma8(c[mt][nt], a[mt], b[nt]);
    }
}

// ---------------- 5: GEMM1  g_xa @ W1 + b1, GELU -> g_h (tf32) -------------------
__global__ __launch_bounds__(256) void k_gemm1(const float* __restrict__ b1) {
    extern __shared__ uint32_t smem[];
    const uint32_t smem_u32 = (uint32_t)__cvta_generic_to_shared(smem);

    int e, tm;
    if (!map_tile(blockIdx.x, e, tm)) return;
    const int row0 = g_offsets[e] + tm * 128;
    int rows = g_offsets[e + 1] - row0;
    if (rows > 128) rows = 128;
    const int col0 = blockIdx.y * 128;

    const float* Ag = g_xa;
    const float* Bg = g_w1t + (size_t)e * DM * HM;
    const int tid = threadIdx.x;
    const int w = tid >> 5, lane = tid & 31;
    const int wm = w >> 1, wn = w & 1;
    const int g = lane >> 2, t = lane & 3;

    float c[2][8][4];
#pragma unroll
    for (int i = 0; i < 2; i++)
#pragma unroll
        for (int j = 0; j < 8; j++)
#pragma unroll
            for (int q = 0; q < 4; q++) c[i][j][q] = 0.f;

    const int S = DM / BK;  // 32
    load_stage(smem_u32, 0, Ag, DM, row0, rows, Bg, HM, col0, 0, tid);
    cpa_commit();
    load_stage(smem_u32, 1, Ag, DM, row0, rows, Bg, HM, col0, BK, tid);
    cpa_commit();
    for (int s = 0; s < S; s++) {
        if (s + 1 < S) cpa_wait1(); else cpa_wait0();
        __syncthreads();
        if (s + 2 < S) {
            load_stage(smem_u32, (s + 2) % NSTG, Ag, DM, row0, rows, Bg, HM,
                       col0, (s + 2) * BK, tid);
            cpa_commit();
        }
        compute_stage(smem, s % NSTG, wm, wn, g, t, c);
    }

#pragma unroll
    for (int mt = 0; mt < 2; mt++) {
        int rl0 = wm * 32 + mt * 16 + g;
#pragma unroll
        for (int half = 0; half < 2; half++) {
            int rl = rl0 + 8 * half;
            if (rl < rows) {
                size_t orow = (size_t)(row0 + rl) * HM;
#pragma unroll
                for (int nt = 0; nt < 8; nt++) {
                    int col = col0 + wn * 64 + nt * 8 + 2 * t;
                    float v0 = c[mt][nt][2 * half + 0] + __ldg(&b1[e * HM + col]);
                    float v1 = c[mt][nt][2 * half + 1] + __ldg(&b1[e * HM + col + 1]);
                    v0 = 0.5f * v0 * (1.f + erff(v0 * 0.70710678118654752f));
                    v1 = 0.5f * v1 * (1.f + erff(v1 * 0.70710678118654752f));
                    float2 o = make_float2(__uint_as_float(f2tf(v0)),
                                           __uint_as_float(f2tf(v1)));
                    *(float2*)&g_h[orow + col] = o;
                }
            }
        }
    }
}

// ---------------- 6: GEMM2  g_h @ W2 + b2 -> out (scatter) -----------------------
__global__ __launch_bounds__(256) void k_gemm2(const float* __restrict__ b2,
                                               float* __restrict__ out) {
    extern __shared__ uint32_t smem[];
    const uint32_t smem_u32 = (uint32_t)__cvta_generic_to_shared(smem);

    int e, tm;
    if (!map_tile(blockIdx.x, e, tm)) return;
    const int row0 = g_offsets[e] + tm * 128;
    int rows = g_offsets[e + 1] - row0;
    if (rows > 128) rows = 128;
    const int col0 = blockIdx.y * 128;

    const float* Ag = g_h;
    const float* Bg = g_w2t + (size_t)e * HM * DM;
    const int tid = threadIdx.x;
    const int w = tid >> 5, lane = tid & 31;
    const int wm = w >> 1, wn = w & 1;
    const int g = lane >> 2, t = lane & 3;

    float c[2][8][4];
#pragma unroll
    for (int i = 0; i < 2; i++)
#pragma unroll
        for (int j = 0; j < 8; j++)
#pragma unroll
            for (int q = 0; q < 4; q++) c[i][j][q] = 0.f;

    const int S = HM / BK;  // 8
    load_stage(smem_u32, 0, Ag, HM, row0, rows, Bg, DM, col0, 0, tid);
    cpa_commit();
    load_stage(smem_u32, 1, Ag, HM, row0, rows, Bg, DM, col0, BK, tid);
    cpa_commit();
    for (int s = 0; s < S; s++) {
        if (s + 1 < S) cpa_wait1(); else cpa_wait0();
        __syncthreads();
        if (s + 2 < S) {
            load_stage(smem_u32, (s + 2) % NSTG, Ag, HM, row0, rows, Bg, DM,
                       col0, (s + 2) * BK, tid);
            cpa_commit();
        }
        compute_stage(smem, s % NSTG, wm, wn, g, t, c);
    }

#pragma unroll
    for (int mt = 0; mt < 2; mt++) {
        int rl0 = wm * 32 + mt * 16 + g;
#pragma unroll
        for (int half = 0; half < 2; half++) {
            int rl = rl0 + 8 * half;
            if (rl < rows) {
                int tok = g_perm[row0 + rl];
                float* orow = out + (size_t)tok * DM;
#pragma unroll
                for (int nt = 0; nt < 8; nt++) {
                    int col = col0 + wn * 64 + nt * 8 + 2 * t;
                    float v0 = c[mt][nt][2 * half + 0] + __ldg(&b2[e * DM + col]);
                    float v1 = c[mt][nt][2 * half + 1] + __ldg(&b2[e * DM + col + 1]);
                    *(float2*)&orow[col] = make_float2(v0, v1);
                }
            }
        }
    }
}

// ---------------- launch ----------------------------------------------------------
extern "C" void kernel_launch(void* const* d_in, const int* in_sizes, int n_in,
                              void* d_out, int out_size) {
    (void)in_sizes; (void)n_in; (void)out_size;
    const float* x  = (const float*)d_in[0];
    const float* Wg = (const float*)d_in[1];
    const float* ls = (const float*)d_in[2];
    const float* lb = (const float*)d_in[3];
    const float* W1 = (const float*)d_in[4];
    const float* b1 = (const float*)d_in[5];
    const float* W2 = (const float*)d_in[6];
    const float* b2 = (const float*)d_in[7];
    float* out = (float*)d_out;

    cudaFuncSetAttribute(k_gemm1, cudaFuncAttributeMaxDynamicSharedMemorySize,
                         SMEM_BYTES);
    cudaFuncSetAttribute(k_gemm2, cudaFuncAttributeMaxDynamicSharedMemorySize,
                         SMEM_BYTES);

    const int MAX_TILES = (N_TOK / 128) + EM;  // 136

    k_zero<<<1, 32>>>();
    k_router<<<N_TOK / 8, 256>>>(x, Wg);
    k_scan<<<1, 1>>>();
    k_wconv<<<(2 * EM * DM * HM / 4) / 256, 256>>>(W1, W2);
    k_scatter<<<N_TOK, 256>>>(x, ls, lb);
    k_gemm1<<<dim3(MAX_TILES, HM / 128), 256, SMEM_BYTES>>>(b1);
    k_gemm2<<<dim3(MAX_TILES, DM / 128), 256, SMEM_BYTES>>>(b2, out);
}

// round 5
// speedup vs baseline: 3.2001x; 1.0650x over previous
#include <cuda_runtime.h>
#include <cuda_bf16.h>
#include <math.h>
#include <stdint.h>

#define N_TOK 16384
#define DM 1024
#define EM 8
#define HM 256

// ---- arch-specific feature detection (tcgen05 availability) -------------------
#if defined(__CUDA_ARCH__) && (__CUDA_ARCH__ == 1000 || __CUDA_ARCH__ == 1030) && \
    (defined(__CUDA_ARCH_FEAT_SM100_ALL) || defined(__CUDA_ARCH_FEAT_SM103_ALL) || \
     defined(__CUDA_ARCH_SPECIFIC__) || defined(__CUDA_ARCH_FAMILY_SPECIFIC__))
#define TC_PATH 1
#else
#define TC_PATH 0
#endif

// ---------------- scratch (device globals; both formats) -----------------------
__device__ float g_xa[(size_t)N_TOK * DM];               // fallback: tf32 A
__device__ float g_h[(size_t)N_TOK * HM];                // fallback: tf32 h
__device__ float g_w1t[(size_t)EM * DM * HM];            // fallback: tf32 W1
__device__ float g_w2t[(size_t)EM * HM * DM];            // fallback: tf32 W2
__device__ __nv_bfloat16 g_a_hi[(size_t)N_TOK * DM];     // tc: A hi/lo
__device__ __nv_bfloat16 g_a_lo[(size_t)N_TOK * DM];
__device__ __nv_bfloat16 g_h_hi[(size_t)N_TOK * HM];
__device__ __nv_bfloat16 g_h_lo[(size_t)N_TOK * HM];
__device__ __nv_bfloat16 g_w1_hi[(size_t)EM * HM * DM];  // tc: W1^T [E][H][D]
__device__ __nv_bfloat16 g_w1_lo[(size_t)EM * HM * DM];
__device__ __nv_bfloat16 g_w2_hi[(size_t)EM * DM * HM];  // tc: W2^T [E][D][H]
__device__ __nv_bfloat16 g_w2_lo[(size_t)EM * DM * HM];
__device__ int   g_top1[N_TOK];
__device__ float g_mu[N_TOK];
__device__ float g_rstd[N_TOK];
__device__ int   g_perm[N_TOK];
__device__ int   g_counts[EM];
__device__ int   g_offsets[EM + 1];
__device__ int   g_cursor[EM];

// ---------------- common helpers -----------------------------------------------
__device__ __forceinline__ uint32_t s2u(const void* p) {
    return (uint32_t)__cvta_generic_to_shared(p);
}
__device__ __forceinline__ uint32_t f2tf(float f) {
    uint32_t u;
    asm("cvt.rna.tf32.f32 %0, %1;" : "=r"(u) : "f"(f));
    return u;
}
__device__ __forceinline__ void cpa16(uint32_t dst, const void* src) {
    asm volatile("cp.async.cg.shared.global [%0], [%1], 16;" ::"r"(dst), "l"(src));
}
__device__ __forceinline__ void cpa_commit() { asm volatile("cp.async.commit_group;"); }
__device__ __forceinline__ void cpa_wait1() { asm volatile("cp.async.wait_group 1;"); }
__device__ __forceinline__ void cpa_wait0() { asm volatile("cp.async.wait_group 0;"); }

__device__ __forceinline__ uint32_t bfpack(__nv_bfloat16 a, __nv_bfloat16 b) {
    uint16_t ua = *(uint16_t*)&a, ub = *(uint16_t*)&b;
    return (uint32_t)ua | ((uint32_t)ub << 16);
}
__device__ __forceinline__ void bfsplit(float v, __nv_bfloat16& h, __nv_bfloat16& l) {
    h = __float2bfloat16(v);
    l = __float2bfloat16(v - __bfloat162float(h));
}

// ---------------- tile -> (expert, tile_m) --------------------------------------
__device__ __forceinline__ bool map_tile(int bx, int& e_out, int& tm_out) {
    int acc = 0;
    int e = -1, tm = 0;
#pragma unroll
    for (int i = 0; i < EM; i++) {
        int cnt = g_offsets[i + 1] - g_offsets[i];
        int te = (cnt + 127) >> 7;
        if (e < 0 && bx < acc + te) { e = i; tm = bx - acc; }
        acc += te;
    }
    e_out = e;
    tm_out = tm;
    return e >= 0;
}

// ---------------- 0: zero --------------------------------------------------------
__global__ void k_zero() {
    if (threadIdx.x < EM) g_counts[threadIdx.x] = 0;
}

// ---------------- 1: router (one warp per token, exact fp32) ----------------------
__global__ __launch_bounds__(256) void k_router(const float* __restrict__ x,
                                                const float* __restrict__ Wg) {
    const int warp = threadIdx.x >> 5, lane = threadIdx.x & 31;
    const int n = blockIdx.x * 8 + warp;
    const float4* xr = (const float4*)(x + (size_t)n * DM);
    const float4* wg = (const float4*)Wg;

    float s = 0.f, ss = 0.f;
    float lg[EM];
#pragma unroll
    for (int e = 0; e < EM; e++) lg[e] = 0.f;

#pragma unroll
    for (int j = 0; j < 8; j++) {
        float4 v = xr[lane + 32 * j];
        s += v.x + v.y + v.z + v.w;
        ss += v.x * v.x + v.y * v.y + v.z * v.z + v.w * v.w;
#pragma unroll
        for (int e = 0; e < EM; e++) {
            float4 w = wg[e * 256 + lane + 32 * j];
            lg[e] += v.x * w.x + v.y * w.y + v.z * w.z + v.w * w.w;
        }
    }
#pragma unroll
    for (int o = 16; o > 0; o >>= 1) {
        s  += __shfl_xor_sync(0xffffffffu, s, o);
        ss += __shfl_xor_sync(0xffffffffu, ss, o);
#pragma unroll
        for (int e = 0; e < EM; e++)
            lg[e] += __shfl_xor_sync(0xffffffffu, lg[e], o);
    }
    if (lane == 0) {
        float mu = s / (float)DM;
        float var = ss / (float)DM - mu * mu;
        int best = 0;
        float bv = lg[0];
#pragma unroll
        for (int e = 1; e < EM; e++)
            if (lg[e] > bv) { bv = lg[e]; best = e; }
        g_top1[n] = best;
        g_mu[n] = mu;
        g_rstd[n] = rsqrtf(var + 1e-5f);
        atomicAdd(&g_counts[best], 1);
    }
}

// ---------------- 2: scan ----------------------------------------------------------
__global__ void k_scan() {
    if (threadIdx.x == 0) {
        int o = 0;
        g_offsets[0] = 0;
#pragma unroll
        for (int e = 0; e < EM; e++) {
            g_cursor[e] = o;
            o += g_counts[e];
            g_offsets[e + 1] = o;
        }
    }
}

// ---------------- 3: weight prep (path-dependent format) ----------------------------
// grid (512, EM), 256 threads
__global__ __launch_bounds__(256) void k_wprep(const float* __restrict__ W1,
                                               const float* __restrict__ W2) {
#if TC_PATH
    // transpose + bf16 split: W1 [E][D][H] -> [E][H][D]; W2 [E][H][D] -> [E][D][H]
    __shared__ float s[32][33];
    const int e = blockIdx.y;
    const int bx = blockIdx.x;
    const float* S;
    __nv_bfloat16 *Dh, *Dl;
    int R, C, tr, tc;
    if (bx < 256) {
        R = DM; C = HM;
        tr = (bx >> 3) * 32;
        tc = (bx & 7) * 32;
        S = W1 + (size_t)e * R * C;
        Dh = g_w1_hi + (size_t)e * R * C;
        Dl = g_w1_lo + (size_t)e * R * C;
    } else {
        int idx = bx - 256;
        R = HM; C = DM;
        tr = (idx >> 5) * 32;
        tc = (idx & 31) * 32;
        S = W2 + (size_t)e * R * C;
        Dh = g_w2_hi + (size_t)e * R * C;
        Dl = g_w2_lo + (size_t)e * R * C;
    }
    const int tx = threadIdx.x & 31, ty = threadIdx.x >> 5;
#pragma unroll
    for (int i = 0; i < 4; i++)
        s[ty + 8 * i][tx] = S[(size_t)(tr + ty + 8 * i) * C + tc + tx];
    __syncthreads();
#pragma unroll
    for (int i = 0; i < 4; i++) {
        float v = s[tx][ty + 8 * i];
        __nv_bfloat16 h, l;
        bfsplit(v, h, l);
        size_t o = (size_t)(tc + ty + 8 * i) * R + tr + tx;
        Dh[o] = h;
        Dl[o] = l;
    }
#else
    // tf32 conversion, same layout
    const int HALF = EM * DM * HM / 4;  // 524288 float4
    int id = (blockIdx.y * 512 + blockIdx.x) * 256 + threadIdx.x;
    const float4* src = (id < HALF) ? (const float4*)W1 : (const float4*)W2;
    float4* dst = (id < HALF) ? (float4*)g_w1t : (float4*)g_w2t;
    int i = (id < HALF) ? id : id - HALF;
    float4 v = src[i];
    float4 o;
    o.x = __uint_as_float(f2tf(v.x));
    o.y = __uint_as_float(f2tf(v.y));
    o.z = __uint_as_float(f2tf(v.z));
    o.w = __uint_as_float(f2tf(v.w));
    dst[i] = o;
#endif
}

// ---------------- 4: scatter (gather + LN affine; path-dependent format) ------------
__global__ __launch_bounds__(256) void k_scatter(const float* __restrict__ x,
                                                 const float* __restrict__ ls,
                                                 const float* __restrict__ lb) {
    const int n = blockIdx.x;
    const int t = threadIdx.x;
    __shared__ int sp, se;
    if (t == 0) {
        int e = g_top1[n];
        int pos = atomicAdd(&g_cursor[e], 1);
        g_perm[pos] = n;
        sp = pos;
        se = e;
    }
    __syncthreads();
    const int pos = sp, e = se;
    const float mu = g_mu[n], rs = g_rstd[n];
    float4 xv = ((const float4*)(x + (size_t)n * DM))[t];
    float4 sv = ((const float4*)(ls + (size_t)e * DM))[t];
    float4 bv = ((const float4*)(lb + (size_t)e * DM))[t];
    float v0 = (xv.x - mu) * rs * sv.x + bv.x;
    float v1 = (xv.y - mu) * rs * sv.y + bv.y;
    float v2 = (xv.z - mu) * rs * sv.z + bv.z;
    float v3 = (xv.w - mu) * rs * sv.w + bv.w;
#if TC_PATH
    __nv_bfloat16 h0, h1, h2, h3, l0, l1, l2, l3;
    bfsplit(v0, h0, l0);
    bfsplit(v1, h1, l1);
    bfsplit(v2, h2, l2);
    bfsplit(v3, h3, l3);
    ((uint2*)(g_a_hi + (size_t)pos * DM))[t] = make_uint2(bfpack(h0, h1), bfpack(h2, h3));
    ((uint2*)(g_a_lo + (size_t)pos * DM))[t] = make_uint2(bfpack(l0, l1), bfpack(l2, l3));
#else
    float4 o;
    o.x = __uint_as_float(f2tf(v0));
    o.y = __uint_as_float(f2tf(v1));
    o.z = __uint_as_float(f2tf(v2));
    o.w = __uint_as_float(f2tf(v3));
    ((float4*)(g_xa + (size_t)pos * DM))[t] = o;
#endif
}

// =====================================================================================
// tcgen05 machinery (compiled only on arch-specific pass)
// =====================================================================================
#if TC_PATH
#define SWZ(o) ((o) ^ (((o) >> 3) & 0x70u))

__device__ __forceinline__ bool elect_one() {
    uint32_t pred;
    asm volatile(
        "{\n\t.reg .pred p;\n\telect.sync _|p, 0xFFFFFFFF;\n\tselp.b32 %0, 1, 0, p;\n\t}"
        : "=r"(pred));
    return pred != 0;
}
__device__ __forceinline__ void mbar_wait(uint32_t addr, uint32_t parity) {
    asm volatile(
        "{\n\t"
        ".reg .pred P;\n\t"
        "LAB_%=:\n\t"
        "mbarrier.try_wait.parity.acquire.cta.shared::cta.b64 P, [%0], %1;\n\t"
        "@!P bra LAB_%=;\n\t"
        "}"
        :: "r"(addr), "r"(parity) : "memory");
}
__device__ __forceinline__ void mma_ss_f16(uint32_t d, uint64_t ad, uint64_t bd,
                                           uint32_t idesc, uint32_t en) {
    asm volatile(
        "{\n\t"
        ".reg .pred p;\n\t"
        "setp.ne.u32 p, %4, 0;\n\t"
        "tcgen05.mma.cta_group::1.kind::f16 [%0], %1, %2, %3, {%5, %5, %5, %5}, p;\n\t"
        "}"
        :: "r"(d), "l"(ad), "l"(bd), "r"(idesc), "r"(en), "r"(0u)
        : "memory");
}
#define LDTM32(r, a)                                                         \
    asm volatile(                                                            \
        "tcgen05.ld.sync.aligned.32x32b.x32.b32 "                            \
        "{%0, %1, %2, %3, %4, %5, %6, %7, "                                  \
        " %8, %9, %10, %11, %12, %13, %14, %15, "                            \
        " %16, %17, %18, %19, %20, %21, %22, %23, "                          \
        " %24, %25, %26, %27, %28, %29, %30, %31}, [%32];"                   \
        : "=r"((r)[0]), "=r"((r)[1]), "=r"((r)[2]), "=r"((r)[3]),            \
          "=r"((r)[4]), "=r"((r)[5]), "=r"((r)[6]), "=r"((r)[7]),            \
          "=r"((r)[8]), "=r"((r)[9]), "=r"((r)[10]), "=r"((r)[11]),          \
          "=r"((r)[12]), "=r"((r)[13]), "=r"((r)[14]), "=r"((r)[15]),        \
          "=r"((r)[16]), "=r"((r)[17]), "=r"((r)[18]), "=r"((r)[19]),        \
          "=r"((r)[20]), "=r"((r)[21]), "=r"((r)[22]), "=r"((r)[23]),        \
          "=r"((r)[24]), "=r"((r)[25]), "=r"((r)[26]), "=r"((r)[27]),        \
          "=r"((r)[28]), "=r"((r)[29]), "=r"((r)[30]), "=r"((r)[31])         \
        : "r"(a))

// SW128 K-major descriptor base
#define DESCB ((2ULL << 61) | (1ULL << 46) | (64ULL << 32) | (1ULL << 16))
// idesc: F32 accum, BF16xBF16, N=256, M=128, cg1
#define IDESC 0x8400490u
#endif  // TC_PATH

#define KC 64
#define A_BYTES 16384
#define B_BYTES 32768
#define STG_BYTES (2 * A_BYTES + 2 * B_BYTES)
#define SMEM_ALLOC (2 * STG_BYTES + 1024)   // 197632 (covers both paths)

// fallback tiling constants
#define BK 32
#define AS_STR 36
#define BS_STR 136
#define A_STAGE (128 * AS_STR)
#define B_STAGE (BK * BS_STR)
#define NSTG 3

#if !TC_PATH
__device__ __forceinline__ void mma8(float* c, const uint32_t* a, const uint32_t* b) {
    asm volatile(
        "mma.sync.aligned.m16n8k8.row.col.f32.tf32.tf32.f32 "
        "{%0,%1,%2,%3},{%4,%5,%6,%7},{%8,%9},{%0,%1,%2,%3};"
        : "+f"(c[0]), "+f"(c[1]), "+f"(c[2]), "+f"(c[3])
        : "r"(a[0]), "r"(a[1]), "r"(a[2]), "r"(a[3]), "r"(b[0]), "r"(b[1]));
}
__device__ __forceinline__ void fb_load_stage(uint32_t smem_u32, int stg,
                                              const float* Ag, int ldA, int row0,
                                              int rows, const float* Bg, int ldB,
                                              int col0, int k0, int tid) {
    uint32_t as_b = smem_u32 + (uint32_t)stg * (A_STAGE * 4);
    uint32_t bs_b = smem_u32 + (uint32_t)(NSTG * A_STAGE + stg * B_STAGE) * 4;
#pragma unroll
    for (int i = 0; i < 4; i++) {
        int id = tid + 256 * i;
        int r = id >> 3, kc = (id & 7) * 4;
        int rr = (r < rows) ? r : rows - 1;
        cpa16(as_b + (uint32_t)(r * AS_STR + kc) * 4,
              Ag + (size_t)(row0 + rr) * ldA + k0 + kc);
    }
#pragma unroll
    for (int i = 0; i < 4; i++) {
        int id = tid + 256 * i;
        int kr = id >> 5, nc = (id & 31) * 4;
        cpa16(bs_b + (uint32_t)(kr * BS_STR + nc) * 4,
              Bg + (size_t)(k0 + kr) * ldB + col0 + nc);
    }
}
__device__ __forceinline__ void fb_compute_stage(const uint32_t* smem, int stg,
                                                 int wm, int wn, int g, int t,
                                                 float c[2][8][4]) {
    const uint32_t* As = smem + stg * A_STAGE;
    const uint32_t* Bs = smem + NSTG * A_STAGE + stg * B_STAGE;
#pragma unroll
    for (int ks = 0; ks < BK; ks += 8) {
        uint32_t a[2][4], b[8][2];
#pragma unroll
        for (int mt = 0; mt < 2; mt++) {
            int m = wm * 32 + mt * 16 + g;
            a[mt][0] = As[m * AS_STR + ks + t];
            a[mt][1] = As[(m + 8) * AS_STR + ks + t];
            a[mt][2] = As[m * AS_STR + ks + t + 4];
            a[mt][3] = As[(m + 8) * AS_STR + ks + t + 4];
        }
#pragma unroll
        for (int nt = 0; nt < 8; nt++) {
            int n = wn * 64 + nt * 8 + g;
            b[nt][0] = Bs[(ks + t) * BS_STR + n];
            b[nt][1] = Bs[(ks + t + 4) * BS_STR + n];
        }
#pragma unroll
        for (int mt = 0; mt < 2; mt++)
#pragma unroll
            for (int nt = 0; nt < 8; nt++)
                mma8(c[mt][nt], a[mt], b[nt]);
    }
}
#endif  // !TC_PATH

// ---------------- 5: GEMM1 -----------------------------------------------------------
// grid (136, 2), 256 threads, SMEM_ALLOC dynamic smem
__global__ __launch_bounds__(256) void k_gemm1(const float* __restrict__ b1) {
    extern __shared__ __align__(16) char dsm[];

#if TC_PATH
    if (blockIdx.y != 0) return;
    __shared__ uint32_t s_tslot;
    __shared__ __align__(8) uint64_t s_mbar;

    int e, tm;
    if (!map_tile(blockIdx.x, e, tm)) return;
    const int row0 = g_offsets[e] + tm * 128;
    int rows = g_offsets[e + 1] - row0;
    if (rows > 128) rows = 128;

    const int tid = threadIdx.x, wid = tid >> 5, lane = tid & 31;
    uint32_t sb = s2u(dsm);
    sb = (sb + 1023u) & ~1023u;
    const uint32_t mbar = s2u(&s_mbar);
    const uint32_t tslot = s2u(&s_tslot);

    if (wid == 0) {
        asm volatile("tcgen05.alloc.cta_group::1.sync.aligned.shared::cta.b32 [%0], %1;"
                     :: "r"(tslot), "r"(256) : "memory");
        asm volatile("tcgen05.relinquish_alloc_permit.cta_group::1.sync.aligned;");
    }
    if (tid == 0)
        asm volatile("mbarrier.init.shared.b64 [%0], 1;" :: "r"(mbar) : "memory");
    __syncthreads();
    uint32_t tb;
    asm volatile("ld.shared.b32 %0, [%1];" : "=r"(tb) : "r"(tslot));

    const __nv_bfloat16* Ah = g_a_hi;
    const __nv_bfloat16* Al = g_a_lo;
    const __nv_bfloat16* Bh = g_w1_hi + (size_t)e * HM * DM;
    const __nv_bfloat16* Bl = g_w1_lo + (size_t)e * HM * DM;

    auto load_stage = [&](int s) {
        uint32_t base = sb + (uint32_t)(s & 1) * STG_BYTES;
        int k0 = s * KC;
#pragma unroll
        for (int i = 0; i < 4; i++) {
            int id = tid + 256 * i;
            int r = id >> 3, c = id & 7;
            int rr = (r < rows) ? r : rows - 1;
            uint32_t off = SWZ((uint32_t)(r * 128 + c * 16));
            cpa16(base + off, Ah + (size_t)(row0 + rr) * DM + k0 + c * 8);
            cpa16(base + A_BYTES + off, Al + (size_t)(row0 + rr) * DM + k0 + c * 8);
        }
#pragma unroll
        for (int i = 0; i < 8; i++) {
            int id = tid + 256 * i;
            int r = id >> 3, c = id & 7;
            uint32_t off = SWZ((uint32_t)(r * 128 + c * 16));
            cpa16(base + 2 * A_BYTES + off, Bh + (size_t)r * DM + k0 + c * 8);
            cpa16(base + 2 * A_BYTES + B_BYTES + off, Bl + (size_t)r * DM + k0 + c * 8);
        }
        cpa_commit();
    };

    const int S = DM / KC;  // 16
    load_stage(0);
    uint32_t ph = 0;
    for (int s = 0; s < S; s++) {
        if (s >= 1) { mbar_wait(mbar, ph); ph ^= 1; }
        if (s + 1 < S) load_stage(s + 1);
        if (s + 1 < S) cpa_wait1(); else cpa_wait0();
        __syncthreads();
        if (wid == 0) {
            asm volatile("fence.proxy.async.shared::cta;" ::: "memory");
            if (elect_one()) {
                uint32_t b = sb + (uint32_t)(s & 1) * STG_BYTES;
                uint64_t ah = DESCB | ((uint64_t)(b >> 4) & 0x3FFF);
                uint64_t al = DESCB | ((uint64_t)((b + A_BYTES) >> 4) & 0x3FFF);
                uint64_t bh = DESCB | ((uint64_t)((b + 2 * A_BYTES) >> 4) & 0x3FFF);
                uint64_t bl = DESCB | ((uint64_t)((b + 2 * A_BYTES + B_BYTES) >> 4) & 0x3FFF);
#pragma unroll
                for (int k = 0; k < 4; k++) {
                    mma_ss_f16(tb, ah + 2 * k, bh + 2 * k, IDESC, (s | k) ? 1u : 0u);
                    mma_ss_f16(tb, ah + 2 * k, bl + 2 * k, IDESC, 1u);
                    mma_ss_f16(tb, al + 2 * k, bh + 2 * k, IDESC, 1u);
                }
                asm volatile(
                    "tcgen05.commit.cta_group::1.mbarrier::arrive::one.shared::cluster.b64 [%0];"
                    :: "r"(mbar) : "memory");
            }
        }
    }
    mbar_wait(mbar, ph);
    asm volatile("tcgen05.fence::after_thread_sync;" ::: "memory");

    if (wid < 4) {
        int rl = wid * 32 + lane;
        bool ok = rl < rows;
        size_t hrow = (size_t)(row0 + rl) * HM;
        const float* bb = b1 + e * HM;
#pragma unroll 1
        for (int cc = 0; cc < 8; cc++) {
            uint32_t r[32];
            LDTM32(r, tb + cc * 32);
            asm volatile("tcgen05.wait::ld.sync.aligned;" ::: "memory");
            if (ok) {
                uint32_t whi[16], wlo[16];
#pragma unroll
                for (int p = 0; p < 16; p++) {
                    float v0 = __uint_as_float(r[2 * p]) + __ldg(&bb[cc * 32 + 2 * p]);
                    float v1 = __uint_as_float(r[2 * p + 1]) + __ldg(&bb[cc * 32 + 2 * p + 1]);
                    v0 = 0.5f * v0 * (1.f + erff(v0 * 0.70710678118654752f));
                    v1 = 0.5f * v1 * (1.f + erff(v1 * 0.70710678118654752f));
                    __nv_bfloat16 h0, h1, l0, l1;
                    bfsplit(v0, h0, l0);
                    bfsplit(v1, h1, l1);
                    whi[p] = bfpack(h0, h1);
                    wlo[p] = bfpack(l0, l1);
                }
                uint4* dh = (uint4*)(g_h_hi + hrow + cc * 32);
                uint4* dl = (uint4*)(g_h_lo + hrow + cc * 32);
#pragma unroll
                for (int q = 0; q < 4; q++) {
                    dh[q] = make_uint4(whi[4 * q], whi[4 * q + 1], whi[4 * q + 2], whi[4 * q + 3]);
                    dl[q] = make_uint4(wlo[4 * q], wlo[4 * q + 1], wlo[4 * q + 2], wlo[4 * q + 3]);
                }
            }
        }
    }
    __syncthreads();
    if (wid == 0)
        asm volatile("tcgen05.dealloc.cta_group::1.sync.aligned.b32 %0, %1;"
                     :: "r"(tb), "r"(256));
#else
    uint32_t* smem = (uint32_t*)dsm;
    const uint32_t smem_u32 = s2u(dsm);

    int e, tm;
    if (!map_tile(blockIdx.x, e, tm)) return;
    const int row0 = g_offsets[e] + tm * 128;
    int rows = g_offsets[e + 1] - row0;
    if (rows > 128) rows = 128;
    const int col0 = blockIdx.y * 128;

    const float* Ag = g_xa;
    const float* Bg = g_w1t + (size_t)e * DM * HM;
    const int tid = threadIdx.x;
    const int w = tid >> 5, lane = tid & 31;
    const int wm = w >> 1, wn = w & 1;
    const int g = lane >> 2, t = lane & 3;

    float c[2][8][4];
#pragma unroll
    for (int i = 0; i < 2; i++)
#pragma unroll
        for (int j = 0; j < 8; j++)
#pragma unroll
            for (int q = 0; q < 4; q++) c[i][j][q] = 0.f;

    const int S = DM / BK;
    fb_load_stage(smem_u32, 0, Ag, DM, row0, rows, Bg, HM, col0, 0, tid);
    cpa_commit();
    fb_load_stage(smem_u32, 1, Ag, DM, row0, rows, Bg, HM, col0, BK, tid);
    cpa_commit();
    for (int s = 0; s < S; s++) {
        if (s + 1 < S) cpa_wait1(); else cpa_wait0();
        __syncthreads();
        if (s + 2 < S) {
            fb_load_stage(smem_u32, (s + 2) % NSTG, Ag, DM, row0, rows, Bg, HM,
                          col0, (s + 2) * BK, tid);
            cpa_commit();
        }
        fb_compute_stage(smem, s % NSTG, wm, wn, g, t, c);
    }

#pragma unroll
    for (int mt = 0; mt < 2; mt++) {
        int rl0 = wm * 32 + mt * 16 + g;
#pragma unroll
        for (int half = 0; half < 2; half++) {
            int rl = rl0 + 8 * half;
            if (rl < rows) {
                size_t orow = (size_t)(row0 + rl) * HM;
#pragma unroll
                for (int nt = 0; nt < 8; nt++) {
                    int col = col0 + wn * 64 + nt * 8 + 2 * t;
                    float v0 = c[mt][nt][2 * half + 0] + __ldg(&b1[e * HM + col]);
                    float v1 = c[mt][nt][2 * half + 1] + __ldg(&b1[e * HM + col + 1]);
                    v0 = 0.5f * v0 * (1.f + erff(v0 * 0.70710678118654752f));
                    v1 = 0.5f * v1 * (1.f + erff(v1 * 0.70710678118654752f));
                    float2 o = make_float2(__uint_as_float(f2tf(v0)),
                                           __uint_as_float(f2tf(v1)));
                    *(float2*)&g_h[orow + col] = o;
                }
            }
        }
    }
#endif
}

// ---------------- 6: GEMM2 ------------------------------------------------------------
// grid (136, 8), 256 threads, SMEM_ALLOC dynamic smem
__global__ __launch_bounds__(256) void k_gemm2(const float* __restrict__ b2,
                                               float* __restrict__ out) {
    extern __shared__ __align__(16) char dsm[];

#if TC_PATH
    if (blockIdx.y >= 4) return;
    __shared__ uint32_t s_tslot;
    __shared__ __align__(8) uint64_t s_mbar;

    int e, tm;
    if (!map_tile(blockIdx.x, e, tm)) return;
    const int row0 = g_offsets[e] + tm * 128;
    int rows = g_offsets[e + 1] - row0;
    if (rows > 128) rows = 128;
    const int col0 = blockIdx.y * 256;

    const int tid = threadIdx.x, wid = tid >> 5, lane = tid & 31;
    uint32_t sb = s2u(dsm);
    sb = (sb + 1023u) & ~1023u;
    const uint32_t mbar = s2u(&s_mbar);
    const uint32_t tslot = s2u(&s_tslot);

    if (wid == 0) {
        asm volatile("tcgen05.alloc.cta_group::1.sync.aligned.shared::cta.b32 [%0], %1;"
                     :: "r"(tslot), "r"(256) : "memory");
        asm volatile("tcgen05.relinquish_alloc_permit.cta_group::1.sync.aligned;");
    }
    if (tid == 0)
        asm volatile("mbarrier.init.shared.b64 [%0], 1;" :: "r"(mbar) : "memory");
    __syncthreads();
    uint32_t tb;
    asm volatile("ld.shared.b32 %0, [%1];" : "=r"(tb) : "r"(tslot));

    const __nv_bfloat16* Ah = g_h_hi;
    const __nv_bfloat16* Al = g_h_lo;
    const __nv_bfloat16* Bh = g_w2_hi + (size_t)e * DM * HM;
    const __nv_bfloat16* Bl = g_w2_lo + (size_t)e * DM * HM;

    auto load_stage = [&](int s) {
        uint32_t base = sb + (uint32_t)(s & 1) * STG_BYTES;
        int k0 = s * KC;
#pragma unroll
        for (int i = 0; i < 4; i++) {
            int id = tid + 256 * i;
            int r = id >> 3, c = id & 7;
            int rr = (r < rows) ? r : rows - 1;
            uint32_t off = SWZ((uint32_t)(r * 128 + c * 16));
            cpa16(base + off, Ah + (size_t)(row0 + rr) * HM + k0 + c * 8);
            cpa16(base + A_BYTES + off, Al + (size_t)(row0 + rr) * HM + k0 + c * 8);
        }
#pragma unroll
        for (int i = 0; i < 8; i++) {
            int id = tid + 256 * i;
            int r = id >> 3, c = id & 7;
            uint32_t off = SWZ((uint32_t)(r * 128 + c * 16));
            cpa16(base + 2 * A_BYTES + off, Bh + (size_t)(col0 + r) * HM + k0 + c * 8);
            cpa16(base + 2 * A_BYTES + B_BYTES + off, Bl + (size_t)(col0 + r) * HM + k0 + c * 8);
        }
        cpa_commit();
    };

    const int S = HM / KC;  // 4
    load_stage(0);
    uint32_t ph = 0;
    for (int s = 0; s < S; s++) {
        if (s >= 1) { mbar_wait(mbar, ph); ph ^= 1; }
        if (s + 1 < S) load_stage(s + 1);
        if (s + 1 < S) cpa_wait1(); else cpa_wait0();
        __syncthreads();
        if (wid == 0) {
            asm volatile("fence.proxy.async.shared::cta;" ::: "memory");
            if (elect_one()) {
                uint32_t b = sb + (uint32_t)(s & 1) * STG_BYTES;
                uint64_t ah = DESCB | ((uint64_t)(b >> 4) & 0x3FFF);
                uint64_t al = DESCB | ((uint64_t)((b + A_BYTES) >> 4) & 0x3FFF);
                uint64_t bh = DESCB | ((uint64_t)((b + 2 * A_BYTES) >> 4) & 0x3FFF);
                uint64_t bl = DESCB | ((uint64_t)((b + 2 * A_BYTES + B_BYTES) >> 4) & 0x3FFF);
#pragma unroll
                for (int k = 0; k < 4; k++) {
                    mma_ss_f16(tb, ah + 2 * k, bh + 2 * k, IDESC, (s | k) ? 1u : 0u);
                    mma_ss_f16(tb, ah + 2 * k, bl + 2 * k, IDESC, 1u);
                    mma_ss_f16(tb, al + 2 * k, bh + 2 * k, IDESC, 1u);
                }
                asm volatile(
                    "tcgen05.commit.cta_group::1.mbarrier::arrive::one.shared::cluster.b64 [%0];"
                    :: "r"(mbar) : "memory");
            }
        }
    }
    mbar_wait(mbar, ph);
    asm volatile("tcgen05.fence::after_thread_sync;" ::: "memory");

    if (wid < 4) {
        int rl = wid * 32 + lane;
        bool ok = rl < rows;
        int tok = ok ? g_perm[row0 + rl] : 0;
        float* orow = out + (size_t)tok * DM + col0;
        const float* bb = b2 + e * DM + col0;
#pragma unroll 1
        for (int cc = 0; cc < 8; cc++) {
            uint32_t r[32];
            LDTM32(r, tb + cc * 32);
            asm volatile("tcgen05.wait::ld.sync.aligned;" ::: "memory");
            if (ok) {
#pragma unroll
                for (int q = 0; q < 8; q++) {
                    float4 v;
                    v.x = __uint_as_float(r[4 * q + 0]) + __ldg(&bb[cc * 32 + 4 * q + 0]);
                    v.y = __uint_as_float(r[4 * q + 1]) + __ldg(&bb[cc * 32 + 4 * q + 1]);
                    v.z = __uint_as_float(r[4 * q + 2]) + __ldg(&bb[cc * 32 + 4 * q + 2]);
                    v.w = __uint_as_float(r[4 * q + 3]) + __ldg(&bb[cc * 32 + 4 * q + 3]);
                    ((float4*)(orow + cc * 32))[q] = v;
                }
            }
        }
    }
    __syncthreads();
    if (wid == 0)
        asm volatile("tcgen05.dealloc.cta_group::1.sync.aligned.b32 %0, %1;"
                     :: "r"(tb), "r"(256));
#else
    uint32_t* smem = (uint32_t*)dsm;
    const uint32_t smem_u32 = s2u(dsm);

    int e, tm;
    if (!map_tile(blockIdx.x, e, tm)) return;
    const int row0 = g_offsets[e] + tm * 128;
    int rows = g_offsets[e + 1] - row0;
    if (rows > 128) rows = 128;
    const int col0 = blockIdx.y * 128;

    const float* Ag = g_h;
    const float* Bg = g_w2t + (size_t)e * HM * DM;
    const int tid = threadIdx.x;
    const int w = tid >> 5, lane = tid & 31;
    const int wm = w >> 1, wn = w & 1;
    const int g = lane >> 2, t = lane & 3;

    float c[2][8][4];
#pragma unroll
    for (int i = 0; i < 2; i++)
#pragma unroll
        for (int j = 0; j < 8; j++)
#pragma unroll
            for (int q = 0; q < 4; q++) c[i][j][q] = 0.f;

    const int S = HM / BK;
    fb_load_stage(smem_u32, 0, Ag, HM, row0, rows, Bg, DM, col0, 0, tid);
    cpa_commit();
    fb_load_stage(smem_u32, 1, Ag, HM, row0, rows, Bg, DM, col0, BK, tid);
    cpa_commit();
    for (int s = 0; s < S; s++) {
        if (s + 1 < S) cpa_wait1(); else cpa_wait0();
        __syncthreads();
        if (s + 2 < S) {
            fb_load_stage(smem_u32, (s + 2) % NSTG, Ag, HM, row0, rows, Bg, DM,
                          col0, (s + 2) * BK, tid);
            cpa_commit();
        }
        fb_compute_stage(smem, s % NSTG, wm, wn, g, t, c);
    }

#pragma unroll
    for (int mt = 0; mt < 2; mt++) {
        int rl0 = wm * 32 + mt * 16 + g;
#pragma unroll
        for (int half = 0; half < 2; half++) {
            int rl = rl0 + 8 * half;
            if (rl < rows) {
                int tok = g_perm[row0 + rl];
                float* orow = out + (size_t)tok * DM;
#pragma unroll
                for (int nt = 0; nt < 8; nt++) {
                    int col = col0 + wn * 64 + nt * 8 + 2 * t;
                    float v0 = c[mt][nt][2 * half + 0] + __ldg(&b2[e * DM + col]);
                    float v1 = c[mt][nt][2 * half + 1] + __ldg(&b2[e * DM + col + 1]);
                    *(float2*)&orow[col] = make_float2(v0, v1);
                }
            }
        }
    }
#endif
}

// ---------------- launch -----------------------------------------------------------------
extern "C" void kernel_launch(void* const* d_in, const int* in_sizes, int n_in,
                              void* d_out, int out_size) {
    (void)in_sizes; (void)n_in; (void)out_size;
    const float* x  = (const float*)d_in[0];
    const float* Wg = (const float*)d_in[1];
    const float* ls = (const float*)d_in[2];
    const float* lb = (const float*)d_in[3];
    const float* W1 = (const float*)d_in[4];
    const float* b1 = (const float*)d_in[5];
    const float* W2 = (const float*)d_in[6];
    const float* b2 = (const float*)d_in[7];
    float* out = (float*)d_out;

    cudaFuncSetAttribute(k_gemm1, cudaFuncAttributeMaxDynamicSharedMemorySize, SMEM_ALLOC);
    cudaFuncSetAttribute(k_gemm2, cudaFuncAttributeMaxDynamicSharedMemorySize, SMEM_ALLOC);

    const int MAX_TILES = (N_TOK / 128) + EM;  // 136

    k_zero<<<1, 32>>>();
    k_router<<<N_TOK / 8, 256>>>(x, Wg);
    k_scan<<<1, 1>>>();
    k_wprep<<<dim3(512, EM), 256>>>(W1, W2);
    k_scatter<<<N_TOK, 256>>>(x, ls, lb);
    k_gemm1<<<dim3(MAX_TILES, 2), 256, SMEM_ALLOC>>>(b1);
    k_gemm2<<<dim3(MAX_TILES, 8), 256, SMEM_ALLOC>>>(b2, out);
}

// round 6
// speedup vs baseline: 3.6656x; 1.1454x over previous
#include <cuda_runtime.h>
#include <cuda_bf16.h>
#include <math.h>
#include <stdint.h>

#define N_TOK 16384
#define DM 1024
#define EM 8
#define HM 256

// ---- arch-specific feature detection (tcgen05 availability) -------------------
#if defined(__CUDA_ARCH__) && (__CUDA_ARCH__ == 1000 || __CUDA_ARCH__ == 1030) && \
    (defined(__CUDA_ARCH_FEAT_SM100_ALL) || defined(__CUDA_ARCH_FEAT_SM103_ALL) || \
     defined(__CUDA_ARCH_SPECIFIC__) || defined(__CUDA_ARCH_FAMILY_SPECIFIC__))
#define TC_PATH 1
#else
#define TC_PATH 0
#endif

// ---------------- scratch (device globals; both formats) -----------------------
__device__ float g_xa[(size_t)N_TOK * DM];               // fallback: tf32 A (token order)
__device__ float g_h[(size_t)N_TOK * HM];                // fallback: tf32 h (gathered order)
__device__ float g_w1t[(size_t)EM * DM * HM];            // fallback: tf32 W1
__device__ float g_w2t[(size_t)EM * HM * DM];            // fallback: tf32 W2
__device__ __nv_bfloat16 g_a_hi[(size_t)N_TOK * DM];     // tc: A hi/lo (token order)
__device__ __nv_bfloat16 g_a_lo[(size_t)N_TOK * DM];
__device__ __nv_bfloat16 g_h_hi[(size_t)N_TOK * HM];     // tc: h hi/lo (gathered order)
__device__ __nv_bfloat16 g_h_lo[(size_t)N_TOK * HM];
__device__ __nv_bfloat16 g_w1_hi[(size_t)EM * HM * DM];  // tc: W1^T [E][H][D]
__device__ __nv_bfloat16 g_w1_lo[(size_t)EM * HM * DM];
__device__ __nv_bfloat16 g_w2_hi[(size_t)EM * DM * HM];  // tc: W2^T [E][D][H]
__device__ __nv_bfloat16 g_w2_lo[(size_t)EM * DM * HM];
__device__ int   g_top1[N_TOK];
__device__ int   g_rank[N_TOK];
__device__ int   g_perm[N_TOK];
__device__ int   g_counts[EM];
__device__ int   g_offsets[EM + 1];

// ---------------- common helpers -----------------------------------------------
__device__ __forceinline__ uint32_t s2u(const void* p) {
    return (uint32_t)__cvta_generic_to_shared(p);
}
__device__ __forceinline__ uint32_t f2tf(float f) {
    uint32_t u;
    asm("cvt.rna.tf32.f32 %0, %1;" : "=r"(u) : "f"(f));
    return u;
}
__device__ __forceinline__ void cpa16(uint32_t dst, const void* src) {
    asm volatile("cp.async.cg.shared.global [%0], [%1], 16;" ::"r"(dst), "l"(src));
}
__device__ __forceinline__ void cpa_commit() { asm volatile("cp.async.commit_group;"); }
__device__ __forceinline__ void cpa_wait2() { asm volatile("cp.async.wait_group 2;"); }
__device__ __forceinline__ void cpa_wait1() { asm volatile("cp.async.wait_group 1;"); }
__device__ __forceinline__ void cpa_wait0() { asm volatile("cp.async.wait_group 0;"); }

__device__ __forceinline__ uint32_t bfpack(__nv_bfloat16 a, __nv_bfloat16 b) {
    uint16_t ua = *(uint16_t*)&a, ub = *(uint16_t*)&b;
    return (uint32_t)ua | ((uint32_t)ub << 16);
}
__device__ __forceinline__ void bfsplit(float v, __nv_bfloat16& h, __nv_bfloat16& l) {
    h = __float2bfloat16(v);
    l = __float2bfloat16(v - __bfloat162float(h));
}

// ---------------- tile -> (expert, tile_m) --------------------------------------
__device__ __forceinline__ bool map_tile(int bx, int& e_out, int& tm_out) {
    int acc = 0;
    int e = -1, tm = 0;
#pragma unroll
    for (int i = 0; i < EM; i++) {
        int cnt = g_offsets[i + 1] - g_offsets[i];
        int te = (cnt + 127) >> 7;
        if (e < 0 && bx < acc + te) { e = i; tm = bx - acc; }
        acc += te;
    }
    e_out = e;
    tm_out = tm;
    return e >= 0;
}

// ---------------- 0: zero --------------------------------------------------------
__global__ void k_zero() {
    if (threadIdx.x < EM) g_counts[threadIdx.x] = 0;
}

// ---------------- 1: fused router + LN + split (one warp per token) ---------------
__global__ __launch_bounds__(256) void k_router(const float* __restrict__ x,
                                                const float* __restrict__ Wg,
                                                const float* __restrict__ ls,
                                                const float* __restrict__ lb) {
    const int warp = threadIdx.x >> 5, lane = threadIdx.x & 31;
    const int n = blockIdx.x * 8 + warp;
    const float4* xr = (const float4*)(x + (size_t)n * DM);
    const float4* wg = (const float4*)Wg;

    float s = 0.f, ss = 0.f;
    float lg[EM];
#pragma unroll
    for (int e = 0; e < EM; e++) lg[e] = 0.f;

    float4 xv[8];
#pragma unroll
    for (int j = 0; j < 8; j++) {
        float4 v = xr[lane + 32 * j];
        xv[j] = v;
        s += v.x + v.y + v.z + v.w;
        ss += v.x * v.x + v.y * v.y + v.z * v.z + v.w * v.w;
#pragma unroll
        for (int e = 0; e < EM; e++) {
            float4 w = wg[e * 256 + lane + 32 * j];
            lg[e] += v.x * w.x + v.y * w.y + v.z * w.z + v.w * w.w;
        }
    }
#pragma unroll
    for (int o = 16; o > 0; o >>= 1) {
        s  += __shfl_xor_sync(0xffffffffu, s, o);
        ss += __shfl_xor_sync(0xffffffffu, ss, o);
#pragma unroll
        for (int e = 0; e < EM; e++)
            lg[e] += __shfl_xor_sync(0xffffffffu, lg[e], o);
    }
    // all lanes hold full sums
    float mu = s / (float)DM;
    float var = ss / (float)DM - mu * mu;
    float rs = rsqrtf(var + 1e-5f);
    int best = 0;
    float bv = lg[0];
#pragma unroll
    for (int e = 1; e < EM; e++)
        if (lg[e] > bv) { bv = lg[e]; best = e; }
    if (lane == 0) {
        g_top1[n] = best;
        g_rank[n] = atomicAdd(&g_counts[best], 1);
    }
    const float4* lsr = (const float4*)(ls + (size_t)best * DM);
    const float4* lbr = (const float4*)(lb + (size_t)best * DM);
#pragma unroll
    for (int j = 0; j < 8; j++) {
        float4 sv = lsr[lane + 32 * j];
        float4 bb = lbr[lane + 32 * j];
        float v0 = (xv[j].x - mu) * rs * sv.x + bb.x;
        float v1 = (xv[j].y - mu) * rs * sv.y + bb.y;
        float v2 = (xv[j].z - mu) * rs * sv.z + bb.z;
        float v3 = (xv[j].w - mu) * rs * sv.w + bb.w;
        size_t idx = (size_t)n * DM + 4 * (lane + 32 * j);
#if TC_PATH
        __nv_bfloat16 h0, h1, h2, h3, l0, l1, l2, l3;
        bfsplit(v0, h0, l0);
        bfsplit(v1, h1, l1);
        bfsplit(v2, h2, l2);
        bfsplit(v3, h3, l3);
        *(uint2*)(g_a_hi + idx) = make_uint2(bfpack(h0, h1), bfpack(h2, h3));
        *(uint2*)(g_a_lo + idx) = make_uint2(bfpack(l0, l1), bfpack(l2, l3));
#else
        float4 o;
        o.x = __uint_as_float(f2tf(v0));
        o.y = __uint_as_float(f2tf(v1));
        o.z = __uint_as_float(f2tf(v2));
        o.w = __uint_as_float(f2tf(v3));
        *(float4*)(g_xa + idx) = o;
#endif
    }
}

// ---------------- 2: scan ----------------------------------------------------------
__global__ void k_scan() {
    if (threadIdx.x == 0) {
        int o = 0;
        g_offsets[0] = 0;
#pragma unroll
        for (int e = 0; e < EM; e++) {
            o += g_counts[e];
            g_offsets[e + 1] = o;
        }
    }
}

// ---------------- 3: perm build (no atomics) ----------------------------------------
__global__ __launch_bounds__(256) void k_perm() {
    int n = blockIdx.x * 256 + threadIdx.x;
    g_perm[g_offsets[g_top1[n]] + g_rank[n]] = n;
}

// ---------------- 4: weight prep -----------------------------------------------------
// grid (512, EM), 256 threads
__global__ __launch_bounds__(256) void k_wprep(const float* __restrict__ W1,
                                               const float* __restrict__ W2) {
#if TC_PATH
    __shared__ float s[32][33];
    const int e = blockIdx.y;
    const int bx = blockIdx.x;
    const float* S;
    __nv_bfloat16 *Dh, *Dl;
    int R, C, tr, tc;
    if (bx < 256) {
        R = DM; C = HM;
        tr = (bx >> 3) * 32;
        tc = (bx & 7) * 32;
        S = W1 + (size_t)e * R * C;
        Dh = g_w1_hi + (size_t)e * R * C;
        Dl = g_w1_lo + (size_t)e * R * C;
    } else {
        int idx = bx - 256;
        R = HM; C = DM;
        tr = (idx >> 5) * 32;
        tc = (idx & 31) * 32;
        S = W2 + (size_t)e * R * C;
        Dh = g_w2_hi + (size_t)e * R * C;
        Dl = g_w2_lo + (size_t)e * R * C;
    }
    const int tx = threadIdx.x & 31, ty = threadIdx.x >> 5;
#pragma unroll
    for (int i = 0; i < 4; i++)
        s[ty + 8 * i][tx] = S[(size_t)(tr + ty + 8 * i) * C + tc + tx];
    __syncthreads();
#pragma unroll
    for (int i = 0; i < 4; i++) {
        float v = s[tx][ty + 8 * i];
        __nv_bfloat16 h, l;
        bfsplit(v, h, l);
        size_t o = (size_t)(tc + ty + 8 * i) * R + tr + tx;
        Dh[o] = h;
        Dl[o] = l;
    }
#else
    const int HALF = EM * DM * HM / 4;
    int id = (blockIdx.y * 512 + blockIdx.x) * 256 + threadIdx.x;
    const float4* src = (id < HALF) ? (const float4*)W1 : (const float4*)W2;
    float4* dst = (id < HALF) ? (float4*)g_w1t : (float4*)g_w2t;
    int i = (id < HALF) ? id : id - HALF;
    float4 v = src[i];
    float4 o;
    o.x = __uint_as_float(f2tf(v.x));
    o.y = __uint_as_float(f2tf(v.y));
    o.z = __uint_as_float(f2tf(v.z));
    o.w = __uint_as_float(f2tf(v.w));
    dst[i] = o;
#endif
}

// =====================================================================================
// tcgen05 machinery
// =====================================================================================
#if TC_PATH
#define SWZ(o) ((o) ^ (((o) >> 3) & 0x70u))

__device__ __forceinline__ bool elect_one() {
    uint32_t pred;
    asm volatile(
        "{\n\t.reg .pred p;\n\telect.sync _|p, 0xFFFFFFFF;\n\tselp.b32 %0, 1, 0, p;\n\t}"
        : "=r"(pred));
    return pred != 0;
}
__device__ __forceinline__ void mbar_wait(uint32_t addr, uint32_t parity) {
    asm volatile(
        "{\n\t"
        ".reg .pred P;\n\t"
        "LAB_%=:\n\t"
        "mbarrier.try_wait.parity.acquire.cta.shared::cta.b64 P, [%0], %1;\n\t"
        "@!P bra LAB_%=;\n\t"
        "}"
        :: "r"(addr), "r"(parity) : "memory");
}
__device__ __forceinline__ void mma_ss_f16(uint32_t d, uint64_t ad, uint64_t bd,
                                           uint32_t idesc, uint32_t en) {
    asm volatile(
        "{\n\t"
        ".reg .pred p;\n\t"
        "setp.ne.u32 p, %4, 0;\n\t"
        "tcgen05.mma.cta_group::1.kind::f16 [%0], %1, %2, %3, {%5, %5, %5, %5}, p;\n\t"
        "}"
        :: "r"(d), "l"(ad), "l"(bd), "r"(idesc), "r"(en), "r"(0u)
        : "memory");
}
#define LDTM32(r, a)                                                         \
    asm volatile(                                                            \
        "tcgen05.ld.sync.aligned.32x32b.x32.b32 "                            \
        "{%0, %1, %2, %3, %4, %5, %6, %7, "                                  \
        " %8, %9, %10, %11, %12, %13, %14, %15, "                            \
        " %16, %17, %18, %19, %20, %21, %22, %23, "                          \
        " %24, %25, %26, %27, %28, %29, %30, %31}, [%32];"                   \
        : "=r"((r)[0]), "=r"((r)[1]), "=r"((r)[2]), "=r"((r)[3]),            \
          "=r"((r)[4]), "=r"((r)[5]), "=r"((r)[6]), "=r"((r)[7]),            \
          "=r"((r)[8]), "=r"((r)[9]), "=r"((r)[10]), "=r"((r)[11]),          \
          "=r"((r)[12]), "=r"((r)[13]), "=r"((r)[14]), "=r"((r)[15]),        \
          "=r"((r)[16]), "=r"((r)[17]), "=r"((r)[18]), "=r"((r)[19]),        \
          "=r"((r)[20]), "=r"((r)[21]), "=r"((r)[22]), "=r"((r)[23]),        \
          "=r"((r)[24]), "=r"((r)[25]), "=r"((r)[26]), "=r"((r)[27]),        \
          "=r"((r)[28]), "=r"((r)[29]), "=r"((r)[30]), "=r"((r)[31])         \
        : "r"(a))

// SW128 K-major descriptor base
#define DESCB ((2ULL << 61) | (1ULL << 46) | (64ULL << 32) | (1ULL << 16))
// idesc: F32 accum, BF16xBF16, N=256, M=128, cg1
#define IDESC 0x8400490u

// KC=32 pipeline: stage = A(128x128B: 64B hi | 64B lo) + B(256x128B)
#define STG2 49152
#define B_OFF2 16384
#endif  // TC_PATH

#define SMEM_ALLOC (4 * 49152 + 1024)   // 197632

// fallback tiling constants
#define BK 32
#define AS_STR 36
#define BS_STR 136
#define A_STAGE (128 * AS_STR)
#define B_STAGE (BK * BS_STR)
#define NSTG 3

#if !TC_PATH
__device__ __forceinline__ void mma8(float* c, const uint32_t* a, const uint32_t* b) {
    asm volatile(
        "mma.sync.aligned.m16n8k8.row.col.f32.tf32.tf32.f32 "
        "{%0,%1,%2,%3},{%4,%5,%6,%7},{%8,%9},{%0,%1,%2,%3};"
        : "+f"(c[0]), "+f"(c[1]), "+f"(c[2]), "+f"(c[3])
        : "r"(a[0]), "r"(a[1]), "r"(a[2]), "r"(a[3]), "r"(b[0]), "r"(b[1]));
}
// perm-gathered A loads: prow = g_perm + row0 (or nullptr => identity rows)
__device__ __forceinline__ void fb_load_stage(uint32_t smem_u32, int stg,
                                              const float* Ag, int ldA, int row0,
                                              int rows, const int* prow,
                                              const float* Bg, int ldB,
                                              int col0, int k0, int tid) {
    uint32_t as_b = smem_u32 + (uint32_t)stg * (A_STAGE * 4);
    uint32_t bs_b = smem_u32 + (uint32_t)(NSTG * A_STAGE + stg * B_STAGE) * 4;
#pragma unroll
    for (int i = 0; i < 4; i++) {
        int id = tid + 256 * i;
        int r = id >> 3, kc = (id & 7) * 4;
        int rr = (r < rows) ? r : rows - 1;
        int grow = prow ? prow[rr] : (row0 + rr);
        cpa16(as_b + (uint32_t)(r * AS_STR + kc) * 4,
              Ag + (size_t)grow * ldA + k0 + kc);
    }
#pragma unroll
    for (int i = 0; i < 4; i++) {
        int id = tid + 256 * i;
        int kr = id >> 5, nc = (id & 31) * 4;
        cpa16(bs_b + (uint32_t)(kr * BS_STR + nc) * 4,
              Bg + (size_t)(k0 + kr) * ldB + col0 + nc);
    }
}
__device__ __forceinline__ void fb_compute_stage(const uint32_t* smem, int stg,
                                                 int wm, int wn, int g, int t,
                                                 float c[2][8][4]) {
    const uint32_t* As = smem + stg * A_STAGE;
    const uint32_t* Bs = smem + NSTG * A_STAGE + stg * B_STAGE;
#pragma unroll
    for (int ks = 0; ks < BK; ks += 8) {
        uint32_t a[2][4], b[8][2];
#pragma unroll
        for (int mt = 0; mt < 2; mt++) {
            int m = wm * 32 + mt * 16 + g;
            a[mt][0] = As[m * AS_STR + ks + t];
            a[mt][1] = As[(m + 8) * AS_STR + ks + t];
            a[mt][2] = As[m * AS_STR + ks + t + 4];
            a[mt][3] = As[(m + 8) * AS_STR + ks + t + 4];
        }
#pragma unroll
        for (int nt = 0; nt < 8; nt++) {
            int n = wn * 64 + nt * 8 + g;
            b[nt][0] = Bs[(ks + t) * BS_STR + n];
            b[nt][1] = Bs[(ks + t + 4) * BS_STR + n];
        }
#pragma unroll
        for (int mt = 0; mt < 2; mt++)
#pragma unroll
            for (int nt = 0; nt < 8; nt++)
                mma8(c[mt][nt], a[mt], b[nt]);
    }
}
#endif  // !TC_PATH

// ---------------- 5: GEMM1 -----------------------------------------------------------
// grid (136, 2), 256 threads
__global__ __launch_bounds__(256) void k_gemm1(const float* __restrict__ b1) {
    extern __shared__ __align__(16) char dsm[];

#if TC_PATH
    if (blockIdx.y != 0) return;
    __shared__ uint32_t s_tslot;
    __shared__ __align__(8) uint64_t s_mbar[2];

    int e, tm;
    if (!map_tile(blockIdx.x, e, tm)) return;
    const int row0 = g_offsets[e] + tm * 128;
    int rows = g_offsets[e + 1] - row0;
    if (rows > 128) rows = 128;

    const int tid = threadIdx.x, wid = tid >> 5, lane = tid & 31;
    uint32_t sb = s2u(dsm);
    sb = (sb + 1023u) & ~1023u;
    const uint32_t mb0 = s2u(&s_mbar[0]);
    const uint32_t mb1 = s2u(&s_mbar[1]);
    const uint32_t tslot = s2u(&s_tslot);

    if (wid == 0) {
        asm volatile("tcgen05.alloc.cta_group::1.sync.aligned.shared::cta.b32 [%0], %1;"
                     :: "r"(tslot), "r"(256) : "memory");
        asm volatile("tcgen05.relinquish_alloc_permit.cta_group::1.sync.aligned;");
    }
    if (tid == 0) {
        asm volatile("mbarrier.init.shared.b64 [%0], 1;" :: "r"(mb0) : "memory");
        asm volatile("mbarrier.init.shared.b64 [%0], 1;" :: "r"(mb1) : "memory");
    }
    __syncthreads();
    uint32_t tb;
    asm volatile("ld.shared.b32 %0, [%1];" : "=r"(tb) : "r"(tslot));

    // per-thread load slots: c = tid&7 fixed; rows r_i = (tid>>3) + 32*i
    const int c = tid & 7;
    const int cq = (c & 3) * 8;                 // element offset within 32-k chunk
    const bool chi = (c < 4);
    const __nv_bfloat16* Asrc[4];
    uint32_t Adst[4];
#pragma unroll
    for (int i = 0; i < 4; i++) {
        int r = (tid >> 3) + 32 * i;
        int rr = (r < rows) ? r : rows - 1;
        int tok = g_perm[row0 + rr];
        Asrc[i] = (chi ? g_a_hi : g_a_lo) + (size_t)tok * DM + cq;
        Adst[i] = SWZ((uint32_t)(r * 128 + c * 16));
    }
    const __nv_bfloat16* Bbase = (chi ? g_w1_hi : g_w1_lo) + (size_t)e * HM * DM + cq;
    uint32_t Bdst[8];
#pragma unroll
    for (int i = 0; i < 8; i++) {
        int r = (tid >> 3) + 32 * i;
        Bdst[i] = B_OFF2 + SWZ((uint32_t)(r * 128 + c * 16));
    }

    auto load_stage = [&](int s) {
        uint32_t base = sb + (uint32_t)(s & 3) * STG2;
        int k0 = s * 32;
#pragma unroll
        for (int i = 0; i < 4; i++)
            cpa16(base + Adst[i], Asrc[i] + k0);
#pragma unroll
        for (int i = 0; i < 8; i++)
            cpa16(base + Bdst[i], Bbase + (size_t)((tid >> 3) + 32 * i) * DM + k0);
        cpa_commit();
    };

    const int S = DM / 32;  // 32
    load_stage(0);
    load_stage(1);
    uint32_t ph[2] = {0u, 0u};
    for (int s = 0; s < S; s++) {
        if (s >= 2) {
            uint32_t m = (s & 1) ? mb1 : mb0;   // commit (s-2) went to mb[(s-2)&1]=mb[s&1]
            mbar_wait(m, ph[s & 1]);
            ph[s & 1] ^= 1;
        }
        if (s + 2 < S) load_stage(s + 2);
        if (s + 2 < S) cpa_wait2();
        else if (s + 1 < S) cpa_wait1();
        else cpa_wait0();
        __syncthreads();
        if (wid == 0) {
            asm volatile("fence.proxy.async.shared::cta;" ::: "memory");
            if (elect_one()) {
                uint32_t b = sb + (uint32_t)(s & 3) * STG2;
                uint64_t ab = DESCB | ((uint64_t)(b >> 4) & 0x3FFF);
                uint64_t bb = DESCB | ((uint64_t)((b + B_OFF2) >> 4) & 0x3FFF);
#pragma unroll
                for (int ks = 0; ks < 2; ks++) {
                    uint64_t ah = ab + 2 * ks, al = ab + 4 + 2 * ks;
                    uint64_t bh = bb + 2 * ks, bl = bb + 4 + 2 * ks;
                    mma_ss_f16(tb, ah, bh, IDESC, (s == 0 && ks == 0) ? 0u : 1u);
                    mma_ss_f16(tb, ah, bl, IDESC, 1u);
                    mma_ss_f16(tb, al, bh, IDESC, 1u);
                }
                uint32_t m = (s & 1) ? mb1 : mb0;
                asm volatile(
                    "tcgen05.commit.cta_group::1.mbarrier::arrive::one.shared::cluster.b64 [%0];"
                    :: "r"(m) : "memory");
            }
        }
    }
    {
        uint32_t mA = (S & 1) ? mb1 : mb0;          // commit S-2
        mbar_wait(mA, ph[S & 1]);
        ph[S & 1] ^= 1;
        uint32_t mBp = ((S - 1) & 1) ? mb1 : mb0;   // commit S-1
        mbar_wait(mBp, ph[(S - 1) & 1]);
        ph[(S - 1) & 1] ^= 1;
    }
    asm volatile("tcgen05.fence::after_thread_sync;" ::: "memory");

    if (wid < 4) {
        int rl = wid * 32 + lane;
        bool ok = rl < rows;
        size_t hrow = (size_t)(row0 + rl) * HM;
        const float* bbp = b1 + e * HM;
#pragma unroll 1
        for (int cc = 0; cc < 8; cc++) {
            uint32_t r[32];
            LDTM32(r, tb + cc * 32);
            asm volatile("tcgen05.wait::ld.sync.aligned;" ::: "memory");
            if (ok) {
                uint32_t whi[16], wlo[16];
#pragma unroll
                for (int p = 0; p < 16; p++) {
                    float v0 = __uint_as_float(r[2 * p]) + __ldg(&bbp[cc * 32 + 2 * p]);
                    float v1 = __uint_as_float(r[2 * p + 1]) + __ldg(&bbp[cc * 32 + 2 * p + 1]);
                    v0 = 0.5f * v0 * (1.f + erff(v0 * 0.70710678118654752f));
                    v1 = 0.5f * v1 * (1.f + erff(v1 * 0.70710678118654752f));
                    __nv_bfloat16 h0, h1, l0, l1;
                    bfsplit(v0, h0, l0);
                    bfsplit(v1, h1, l1);
                    whi[p] = bfpack(h0, h1);
                    wlo[p] = bfpack(l0, l1);
                }
                uint4* dh = (uint4*)(g_h_hi + hrow + cc * 32);
                uint4* dl = (uint4*)(g_h_lo + hrow + cc * 32);
#pragma unroll
                for (int q = 0; q < 4; q++) {
                    dh[q] = make_uint4(whi[4 * q], whi[4 * q + 1], whi[4 * q + 2], whi[4 * q + 3]);
                    dl[q] = make_uint4(wlo[4 * q], wlo[4 * q + 1], wlo[4 * q + 2], wlo[4 * q + 3]);
                }
            }
        }
    }
    __syncthreads();
    if (wid == 0)
        asm volatile("tcgen05.dealloc.cta_group::1.sync.aligned.b32 %0, %1;"
                     :: "r"(tb), "r"(256));
#else
    uint32_t* smem = (uint32_t*)dsm;
    const uint32_t smem_u32 = s2u(dsm);

    int e, tm;
    if (!map_tile(blockIdx.x, e, tm)) return;
    const int row0 = g_offsets[e] + tm * 128;
    int rows = g_offsets[e + 1] - row0;
    if (rows > 128) rows = 128;
    const int col0 = blockIdx.y * 128;
    const int* prow = g_perm + row0;

    const float* Ag = g_xa;
    const float* Bg = g_w1t + (size_t)e * DM * HM;
    const int tid = threadIdx.x;
    const int w = tid >> 5, lane = tid & 31;
    const int wm = w >> 1, wn = w & 1;
    const int g = lane >> 2, t = lane & 3;

    float c[2][8][4];
#pragma unroll
    for (int i = 0; i < 2; i++)
#pragma unroll
        for (int j = 0; j < 8; j++)
#pragma unroll
            for (int q = 0; q < 4; q++) c[i][j][q] = 0.f;

    const int S = DM / BK;
    fb_load_stage(smem_u32, 0, Ag, DM, row0, rows, prow, Bg, HM, col0, 0, tid);
    cpa_commit();
    fb_load_stage(smem_u32, 1, Ag, DM, row0, rows, prow, Bg, HM, col0, BK, tid);
    cpa_commit();
    for (int s = 0; s < S; s++) {
        if (s + 1 < S) cpa_wait1(); else cpa_wait0();
        __syncthreads();
        if (s + 2 < S) {
            fb_load_stage(smem_u32, (s + 2) % NSTG, Ag, DM, row0, rows, prow, Bg, HM,
                          col0, (s + 2) * BK, tid);
            cpa_commit();
        }
        fb_compute_stage(smem, s % NSTG, wm, wn, g, t, c);
    }

#pragma unroll
    for (int mt = 0; mt < 2; mt++) {
        int rl0 = wm * 32 + mt * 16 + g;
#pragma unroll
        for (int half = 0; half < 2; half++) {
            int rl = rl0 + 8 * half;
            if (rl < rows) {
                size_t orow = (size_t)(row0 + rl) * HM;
#pragma unroll
                for (int nt = 0; nt < 8; nt++) {
                    int col = col0 + wn * 64 + nt * 8 + 2 * t;
                    float v0 = c[mt][nt][2 * half + 0] + __ldg(&b1[e * HM + col]);
                    float v1 = c[mt][nt][2 * half + 1] + __ldg(&b1[e * HM + col + 1]);
                    v0 = 0.5f * v0 * (1.f + erff(v0 * 0.70710678118654752f));
                    v1 = 0.5f * v1 * (1.f + erff(v1 * 0.70710678118654752f));
                    float2 o = make_float2(__uint_as_float(f2tf(v0)),
                                           __uint_as_float(f2tf(v1)));
                    *(float2*)&g_h[orow + col] = o;
                }
            }
        }
    }
#endif
}

// ---------------- 6: GEMM2 ------------------------------------------------------------
// grid (136, 8), 256 threads
__global__ __launch_bounds__(256) void k_gemm2(const float* __restrict__ b2,
                                               float* __restrict__ out) {
    extern __shared__ __align__(16) char dsm[];

#if TC_PATH
    if (blockIdx.y >= 4) return;
    __shared__ uint32_t s_tslot;
    __shared__ __align__(8) uint64_t s_mbar[2];

    int e, tm;
    if (!map_tile(blockIdx.x, e, tm)) return;
    const int row0 = g_offsets[e] + tm * 128;
    int rows = g_offsets[e + 1] - row0;
    if (rows > 128) rows = 128;
    const int col0 = blockIdx.y * 256;

    const int tid = threadIdx.x, wid = tid >> 5, lane = tid & 31;
    uint32_t sb = s2u(dsm);
    sb = (sb + 1023u) & ~1023u;
    const uint32_t mb0 = s2u(&s_mbar[0]);
    const uint32_t mb1 = s2u(&s_mbar[1]);
    const uint32_t tslot = s2u(&s_tslot);

    if (wid == 0) {
        asm volatile("tcgen05.alloc.cta_group::1.sync.aligned.shared::cta.b32 [%0], %1;"
                     :: "r"(tslot), "r"(256) : "memory");
        asm volatile("tcgen05.relinquish_alloc_permit.cta_group::1.sync.aligned;");
    }
    if (tid == 0) {
        asm volatile("mbarrier.init.shared.b64 [%0], 1;" :: "r"(mb0) : "memory");
        asm volatile("mbarrier.init.shared.b64 [%0], 1;" :: "r"(mb1) : "memory");
    }
    __syncthreads();
    uint32_t tb;
    asm volatile("ld.shared.b32 %0, [%1];" : "=r"(tb) : "r"(tslot));

    const int c = tid & 7;
    const int cq = (c & 3) * 8;
    const bool chi = (c < 4);
    const __nv_bfloat16* Asrc[4];
    uint32_t Adst[4];
#pragma unroll
    for (int i = 0; i < 4; i++) {
        int r = (tid >> 3) + 32 * i;
        int rr = (r < rows) ? r : rows - 1;
        Asrc[i] = (chi ? g_h_hi : g_h_lo) + (size_t)(row0 + rr) * HM + cq;
        Adst[i] = SWZ((uint32_t)(r * 128 + c * 16));
    }
    const __nv_bfloat16* Bbase =
        (chi ? g_w2_hi : g_w2_lo) + (size_t)e * DM * HM + (size_t)col0 * HM + cq;
    uint32_t Bdst[8];
#pragma unroll
    for (int i = 0; i < 8; i++) {
        int r = (tid >> 3) + 32 * i;
        Bdst[i] = B_OFF2 + SWZ((uint32_t)(r * 128 + c * 16));
    }

    auto load_stage = [&](int s) {
        uint32_t base = sb + (uint32_t)(s & 3) * STG2;
        int k0 = s * 32;
#pragma unroll
        for (int i = 0; i < 4; i++)
            cpa16(base + Adst[i], Asrc[i] + k0);
#pragma unroll
        for (int i = 0; i < 8; i++)
            cpa16(base + Bdst[i], Bbase + (size_t)((tid >> 3) + 32 * i) * HM + k0);
        cpa_commit();
    };

    const int S = HM / 32;  // 8
    load_stage(0);
    load_stage(1);
    uint32_t ph[2] = {0u, 0u};
    for (int s = 0; s < S; s++) {
        if (s >= 2) {
            uint32_t m = (s & 1) ? mb1 : mb0;
            mbar_wait(m, ph[s & 1]);
            ph[s & 1] ^= 1;
        }
        if (s + 2 < S) load_stage(s + 2);
        if (s + 2 < S) cpa_wait2();
        else if (s + 1 < S) cpa_wait1();
        else cpa_wait0();
        __syncthreads();
        if (wid == 0) {
            asm volatile("fence.proxy.async.shared::cta;" ::: "memory");
            if (elect_one()) {
                uint32_t b = sb + (uint32_t)(s & 3) * STG2;
                uint64_t ab = DESCB | ((uint64_t)(b >> 4) & 0x3FFF);
                uint64_t bb = DESCB | ((uint64_t)((b + B_OFF2) >> 4) & 0x3FFF);
#pragma unroll
                for (int ks = 0; ks < 2; ks++) {
                    uint64_t ah = ab + 2 * ks, al = ab + 4 + 2 * ks;
                    uint64_t bh = bb + 2 * ks, bl = bb + 4 + 2 * ks;
                    mma_ss_f16(tb, ah, bh, IDESC, (s == 0 && ks == 0) ? 0u : 1u);
                    mma_ss_f16(tb, ah, bl, IDESC, 1u);
                    mma_ss_f16(tb, al, bh, IDESC, 1u);
                }
                uint32_t m = (s & 1) ? mb1 : mb0;
                asm volatile(
                    "tcgen05.commit.cta_group::1.mbarrier::arrive::one.shared::cluster.b64 [%0];"
                    :: "r"(m) : "memory");
            }
        }
    }
    {
        uint32_t mA = (S & 1) ? mb1 : mb0;
        mbar_wait(mA, ph[S & 1]);
        ph[S & 1] ^= 1;
        uint32_t mBp = ((S - 1) & 1) ? mb1 : mb0;
        mbar_wait(mBp, ph[(S - 1) & 1]);
        ph[(S - 1) & 1] ^= 1;
    }
    asm volatile("tcgen05.fence::after_thread_sync;" ::: "memory");

    if (wid < 4) {
        int rl = wid * 32 + lane;
        bool ok = rl < rows;
        int tok = ok ? g_perm[row0 + rl] : 0;
        float* orow = out + (size_t)tok * DM + col0;
        const float* bbp = b2 + e * DM + col0;
#pragma unroll 1
        for (int cc = 0; cc < 8; cc++) {
            uint32_t r[32];
            LDTM32(r, tb + cc * 32);
            asm volatile("tcgen05.wait::ld.sync.aligned;" ::: "memory");
            if (ok) {
#pragma unroll
                for (int q = 0; q < 8; q++) {
                    float4 v;
                    v.x = __uint_as_float(r[4 * q + 0]) + __ldg(&bbp[cc * 32 + 4 * q + 0]);
                    v.y = __uint_as_float(r[4 * q + 1]) + __ldg(&bbp[cc * 32 + 4 * q + 1]);
                    v.z = __uint_as_float(r[4 * q + 2]) + __ldg(&bbp[cc * 32 + 4 * q + 2]);
                    v.w = __uint_as_float(r[4 * q + 3]) + __ldg(&bbp[cc * 32 + 4 * q + 3]);
                    ((float4*)(orow + cc * 32))[q] = v;
                }
            }
        }
    }
    __syncthreads();
    if (wid == 0)
        asm volatile("tcgen05.dealloc.cta_group::1.sync.aligned.b32 %0, %1;"
                     :: "r"(tb), "r"(256));
#else
    uint32_t* smem = (uint32_t*)dsm;
    const uint32_t smem_u32 = s2u(dsm);

    int e, tm;
    if (!map_tile(blockIdx.x, e, tm)) return;
    const int row0 = g_offsets[e] + tm * 128;
    int rows = g_offsets[e + 1] - row0;
    if (rows > 128) rows = 128;
    const int col0 = blockIdx.y * 128;

    const float* Ag = g_h;
    const float* Bg = g_w2t + (size_t)e * HM * DM;
    const int tid = threadIdx.x;
    const int w = tid >> 5, lane = tid & 31;
    const int wm = w >> 1, wn = w & 1;
    const int g = lane >> 2, t = lane & 3;

    float c[2][8][4];
#pragma unroll
    for (int i = 0; i < 2; i++)
#pragma unroll
        for (int j = 0; j < 8; j++)
#pragma unroll
            for (int q = 0; q < 4; q++) c[i][j][q] = 0.f;

    const int S = HM / BK;
    fb_load_stage(smem_u32, 0, Ag, HM, row0, rows, nullptr, Bg, DM, col0, 0, tid);
    cpa_commit();
    fb_load_stage(smem_u32, 1, Ag, HM, row0, rows, nullptr, Bg, DM, col0, BK, tid);
    cpa_commit();
    for (int s = 0; s < S; s++) {
        if (s + 1 < S) cpa_wait1(); else cpa_wait0();
        __syncthreads();
        if (s + 2 < S) {
            fb_load_stage(smem_u32, (s + 2) % NSTG, Ag, HM, row0, rows, nullptr, Bg, DM,
                          col0, (s + 2) * BK, tid);
            cpa_commit();
        }
        fb_compute_stage(smem, s % NSTG, wm, wn, g, t, c);
    }

#pragma unroll
    for (int mt = 0; mt < 2; mt++) {
        int rl0 = wm * 32 + mt * 16 + g;
#pragma unroll
        for (int half = 0; half < 2; half++) {
            int rl = rl0 + 8 * half;
            if (rl < rows) {
                int tok = g_perm[row0 + rl];
                float* orow = out + (size_t)tok * DM;
#pragma unroll
                for (int nt = 0; nt < 8; nt++) {
                    int col = col0 + wn * 64 + nt * 8 + 2 * t;
                    float v0 = c[mt][nt][2 * half + 0] + __ldg(&b2[e * DM + col]);
                    float v1 = c[mt][nt][2 * half + 1] + __ldg(&b2[e * DM + col + 1]);
                    *(float2*)&orow[col] = make_float2(v0, v1);
                }
            }
        }
    }
#endif
}

// ---------------- launch -----------------------------------------------------------------
extern "C" void kernel_launch(void* const* d_in, const int* in_sizes, int n_in,
                              void* d_out, int out_size) {
    (void)in_sizes; (void)n_in; (void)out_size;
    const float* x  = (const float*)d_in[0];
    const float* Wg = (const float*)d_in[1];
    const float* ls = (const float*)d_in[2];
    const float* lb = (const float*)d_in[3];
    const float* W1 = (const float*)d_in[4];
    const float* b1 = (const float*)d_in[5];
    const float* W2 = (const float*)d_in[6];
    const float* b2 = (const float*)d_in[7];
    float* out = (float*)d_out;

    cudaFuncSetAttribute(k_gemm1, cudaFuncAttributeMaxDynamicSharedMemorySize, SMEM_ALLOC);
    cudaFuncSetAttribute(k_gemm2, cudaFuncAttributeMaxDynamicSharedMemorySize, SMEM_ALLOC);

    const int MAX_TILES = (N_TOK / 128) + EM;  // 136

    k_zero<<<1, 32>>>();
    k_router<<<N_TOK / 8, 256>>>(x, Wg, ls, lb);
    k_scan<<<1, 1>>>();
    k_perm<<<N_TOK / 256, 256>>>();
    k_wprep<<<dim3(512, EM), 256>>>(W1, W2);
    k_gemm1<<<dim3(MAX_TILES, 2), 256, SMEM_ALLOC>>>(b1);
    k_gemm2<<<dim3(MAX_TILES, 8), 256, SMEM_ALLOC>>>(b2, out);
}

// round 8
// speedup vs baseline: 3.7169x; 1.0140x over previous
#include <cuda_runtime.h>
#include <cuda_bf16.h>
#include <math.h>
#include <stdint.h>

#define N_TOK 16384
#define DM 1024
#define EM 8
#define HM 256

// ---- arch-specific feature detection (tcgen05 availability) -------------------
#if defined(__CUDA_ARCH__) && (__CUDA_ARCH__ == 1000 || __CUDA_ARCH__ == 1030) && \
    (defined(__CUDA_ARCH_FEAT_SM100_ALL) || defined(__CUDA_ARCH_FEAT_SM103_ALL) || \
     defined(__CUDA_ARCH_SPECIFIC__) || defined(__CUDA_ARCH_FAMILY_SPECIFIC__))
#define TC_PATH 1
#else
#define TC_PATH 0
#endif

// ---------------- scratch (device globals; both formats) -----------------------
__device__ float g_xa[(size_t)N_TOK * DM];               // fallback: tf32 A (token order)
__device__ float g_h[(size_t)N_TOK * HM];                // fallback: tf32 h (gathered)
__device__ float g_w1t[(size_t)EM * DM * HM];            // fallback: tf32 W1
__device__ float g_w2t[(size_t)EM * HM * DM];            // fallback: tf32 W2
__device__ __nv_bfloat16 g_a_hi[(size_t)N_TOK * DM];     // tc: A hi/lo (token order)
__device__ __nv_bfloat16 g_a_lo[(size_t)N_TOK * DM];
__device__ __nv_bfloat16 g_h_hi[(size_t)N_TOK * HM];     // tc: h hi/lo (gathered)
__device__ __nv_bfloat16 g_h_lo[(size_t)N_TOK * HM];
__device__ __nv_bfloat16 g_w1_hi[(size_t)EM * HM * DM];  // tc: W1^T [E][H][D]
__device__ __nv_bfloat16 g_w1_lo[(size_t)EM * HM * DM];
__device__ __nv_bfloat16 g_w2_hi[(size_t)EM * DM * HM];  // tc: W2^T [E][D][H]
__device__ __nv_bfloat16 g_w2_lo[(size_t)EM * DM * HM];
__device__ int   g_top1[N_TOK];
__device__ int   g_rank[N_TOK];
__device__ int   g_perm[N_TOK];
__device__ int   g_counts[EM];

// ---------------- common helpers -----------------------------------------------
__device__ __forceinline__ uint32_t s2u(const void* p) {
    return (uint32_t)__cvta_generic_to_shared(p);
}
__device__ __forceinline__ uint32_t f2tf(float f) {
    uint32_t u;
    asm("cvt.rna.tf32.f32 %0, %1;" : "=r"(u) : "f"(f));
    return u;
}
__device__ __forceinline__ void cpa16(uint32_t dst, const void* src) {
    asm volatile("cp.async.cg.shared.global [%0], [%1], 16;" ::"r"(dst), "l"(src));
}
__device__ __forceinline__ void cpa_commit() { asm volatile("cp.async.commit_group;"); }
__device__ __forceinline__ void cpa_wait2() { asm volatile("cp.async.wait_group 2;"); }
__device__ __forceinline__ void cpa_wait1() { asm volatile("cp.async.wait_group 1;"); }
__device__ __forceinline__ void cpa_wait0() { asm volatile("cp.async.wait_group 0;"); }

__device__ __forceinline__ uint32_t bfpack(__nv_bfloat16 a, __nv_bfloat16 b) {
    uint16_t ua = *(uint16_t*)&a, ub = *(uint16_t*)&b;
    return (uint32_t)ua | ((uint32_t)ub << 16);
}
__device__ __forceinline__ void bfsplit(float v, __nv_bfloat16& h, __nv_bfloat16& l) {
    h = __float2bfloat16(v);
    l = __float2bfloat16(v - __bfloat162float(h));
}

// ---------------- tile -> (expert, row0, rows) from g_counts ---------------------
__device__ __forceinline__ bool map_tile(int bx, int& e_out, int& row0_out,
                                         int& rows_out) {
    int acc = 0, off = 0, e = -1, row0 = 0, rows = 0;
#pragma unroll
    for (int i = 0; i < EM; i++) {
        int cnt = g_counts[i];
        int te = (cnt + 127) >> 7;
        if (e < 0 && bx < acc + te) {
            int tm = bx - acc;
            e = i;
            row0 = off + tm * 128;
            rows = cnt - tm * 128;
            if (rows > 128) rows = 128;
        }
        acc += te;
        off += cnt;
    }
    e_out = e;
    row0_out = row0;
    rows_out = rows;
    return e >= 0;
}

// ---------------- 0: zero --------------------------------------------------------
__global__ void k_zero() {
    if (threadIdx.x < EM) g_counts[threadIdx.x] = 0;
}

// ---------------- 1: fused router + LN + split (one warp per token) ---------------
__global__ __launch_bounds__(256) void k_router(const float* __restrict__ x,
                                                const float* __restrict__ Wg,
                                                const float* __restrict__ ls,
                                                const float* __restrict__ lb) {
    const int warp = threadIdx.x >> 5, lane = threadIdx.x & 31;
    const int n = blockIdx.x * 8 + warp;
    const float4* xr = (const float4*)(x + (size_t)n * DM);
    const float4* wg = (const float4*)Wg;

    float s = 0.f, ss = 0.f;
    float lg[EM];
#pragma unroll
    for (int e = 0; e < EM; e++) lg[e] = 0.f;

    float4 xv[8];
#pragma unroll
    for (int j = 0; j < 8; j++) {
        float4 v = xr[lane + 32 * j];
        xv[j] = v;
        s += v.x + v.y + v.z + v.w;
        ss += v.x * v.x + v.y * v.y + v.z * v.z + v.w * v.w;
#pragma unroll
        for (int e = 0; e < EM; e++) {
            float4 w = wg[e * 256 + lane + 32 * j];
            lg[e] += v.x * w.x + v.y * w.y + v.z * w.z + v.w * w.w;
        }
    }
#pragma unroll
    for (int o = 16; o > 0; o >>= 1) {
        s  += __shfl_xor_sync(0xffffffffu, s, o);
        ss += __shfl_xor_sync(0xffffffffu, ss, o);
#pragma unroll
        for (int e = 0; e < EM; e++)
            lg[e] += __shfl_xor_sync(0xffffffffu, lg[e], o);
    }
    float mu = s / (float)DM;
    float var = ss / (float)DM - mu * mu;
    float rs = rsqrtf(var + 1e-5f);
    int best = 0;
    float bv = lg[0];
#pragma unroll
    for (int e = 1; e < EM; e++)
        if (lg[e] > bv) { bv = lg[e]; best = e; }
    if (lane == 0) {
        g_top1[n] = best;
        g_rank[n] = atomicAdd(&g_counts[best], 1);
    }
    const float4* lsr = (const float4*)(ls + (size_t)best * DM);
    const float4* lbr = (const float4*)(lb + (size_t)best * DM);
#pragma unroll
    for (int j = 0; j < 8; j++) {
        float4 sv = lsr[lane + 32 * j];
        float4 bb = lbr[lane + 32 * j];
        float v0 = (xv[j].x - mu) * rs * sv.x + bb.x;
        float v1 = (xv[j].y - mu) * rs * sv.y + bb.y;
        float v2 = (xv[j].z - mu) * rs * sv.z + bb.z;
        float v3 = (xv[j].w - mu) * rs * sv.w + bb.w;
        size_t idx = (size_t)n * DM + 4 * (lane + 32 * j);
#if TC_PATH
        __nv_bfloat16 h0, h1, h2, h3, l0, l1, l2, l3;
        bfsplit(v0, h0, l0);
        bfsplit(v1, h1, l1);
        bfsplit(v2, h2, l2);
        bfsplit(v3, h3, l3);
        *(uint2*)(g_a_hi + idx) = make_uint2(bfpack(h0, h1), bfpack(h2, h3));
        *(uint2*)(g_a_lo + idx) = make_uint2(bfpack(l0, l1), bfpack(l2, l3));
#else
        float4 o;
        o.x = __uint_as_float(f2tf(v0));
        o.y = __uint_as_float(f2tf(v1));
        o.z = __uint_as_float(f2tf(v2));
        o.w = __uint_as_float(f2tf(v3));
        *(float4*)(g_xa + idx) = o;
#endif
    }
}

// ---------------- 2: perm build (offsets computed locally; no scan kernel) ---------
__global__ __launch_bounds__(256) void k_perm() {
    int n = blockIdx.x * 256 + threadIdx.x;
    int e = g_top1[n];
    int off = 0;
#pragma unroll
    for (int i = 0; i < EM; i++)
        if (i < e) off += g_counts[i];
    g_perm[off + g_rank[n]] = n;
}

// ---------------- 3: weight prep -----------------------------------------------------
// grid (512, EM), 256 threads
__global__ __launch_bounds__(256) void k_wprep(const float* __restrict__ W1,
                                               const float* __restrict__ W2) {
#if TC_PATH
    __shared__ float s[32][33];
    const int e = blockIdx.y;
    const int bx = blockIdx.x;
    const float* S;
    __nv_bfloat16 *Dh, *Dl;
    int R, C, tr, tc;
    if (bx < 256) {
        R = DM; C = HM;
        tr = (bx >> 3) * 32;
        tc = (bx & 7) * 32;
        S = W1 + (size_t)e * R * C;
        Dh = g_w1_hi + (size_t)e * R * C;
        Dl = g_w1_lo + (size_t)e * R * C;
    } else {
        int idx = bx - 256;
        R = HM; C = DM;
        tr = (idx >> 5) * 32;
        tc = (idx & 31) * 32;
        S = W2 + (size_t)e * R * C;
        Dh = g_w2_hi + (size_t)e * R * C;
        Dl = g_w2_lo + (size_t)e * R * C;
    }
    const int tx = threadIdx.x & 31, ty = threadIdx.x >> 5;
#pragma unroll
    for (int i = 0; i < 4; i++)
        s[ty + 8 * i][tx] = S[(size_t)(tr + ty + 8 * i) * C + tc + tx];
    __syncthreads();
#pragma unroll
    for (int i = 0; i < 4; i++) {
        float v = s[tx][ty + 8 * i];
        __nv_bfloat16 h, l;
        bfsplit(v, h, l);
        size_t o = (size_t)(tc + ty + 8 * i) * R + tr + tx;
        Dh[o] = h;
        Dl[o] = l;
    }
#else
    const int HALF = EM * DM * HM / 4;
    int id = (blockIdx.y * 512 + blockIdx.x) * 256 + threadIdx.x;
    const float4* src = (id < HALF) ? (const float4*)W1 : (const float4*)W2;
    float4* dst = (id < HALF) ? (float4*)g_w1t : (float4*)g_w2t;
    int i = (id < HALF) ? id : id - HALF;
    float4 v = src[i];
    float4 o;
    o.x = __uint_as_float(f2tf(v.x));
    o.y = __uint_as_float(f2tf(v.y));
    o.z = __uint_as_float(f2tf(v.z));
    o.w = __uint_as_float(f2tf(v.w));
    dst[i] = o;
#endif
}

// =====================================================================================
// tcgen05 machinery
// =====================================================================================
#if TC_PATH
#define SWZ(o) ((o) ^ (((o) >> 3) & 0x70u))

__device__ __forceinline__ bool elect_one() {
    uint32_t pred;
    asm volatile(
        "{\n\t.reg .pred p;\n\telect.sync _|p, 0xFFFFFFFF;\n\tselp.b32 %0, 1, 0, p;\n\t}"
        : "=r"(pred));
    return pred != 0;
}
__device__ __forceinline__ void mbar_wait(uint32_t addr, uint32_t parity) {
    asm volatile(
        "{\n\t"
        ".reg .pred P;\n\t"
        "LAB_%=:\n\t"
        "mbarrier.try_wait.parity.acquire.cta.shared::cta.b64 P, [%0], %1;\n\t"
        "@!P bra LAB_%=;\n\t"
        "}"
        :: "r"(addr), "r"(parity) : "memory");
}
__device__ __forceinline__ void mma_ss_f16(uint32_t d, uint64_t ad, uint64_t bd,
                                           uint32_t idesc, uint32_t en) {
    asm volatile(
        "{\n\t"
        ".reg .pred p;\n\t"
        "setp.ne.u32 p, %4, 0;\n\t"
        "tcgen05.mma.cta_group::1.kind::f16 [%0], %1, %2, %3, {%5, %5, %5, %5}, p;\n\t"
        "}"
        :: "r"(d), "l"(ad), "l"(bd), "r"(idesc), "r"(en), "r"(0u)
        : "memory");
}
#define LDTM32(r, a)                                                         \
    asm volatile(                                                            \
        "tcgen05.ld.sync.aligned.32x32b.x32.b32 "                            \
        "{%0, %1, %2, %3, %4, %5, %6, %7, "                                  \
        " %8, %9, %10, %11, %12, %13, %14, %15, "                            \
        " %16, %17, %18, %19, %20, %21, %22, %23, "                          \
        " %24, %25, %26, %27, %28, %29, %30, %31}, [%32];"                   \
        : "=r"((r)[0]), "=r"((r)[1]), "=r"((r)[2]), "=r"((r)[3]),            \
          "=r"((r)[4]), "=r"((r)[5]), "=r"((r)[6]), "=r"((r)[7]),            \
          "=r"((r)[8]), "=r"((r)[9]), "=r"((r)[10]), "=r"((r)[11]),          \
          "=r"((r)[12]), "=r"((r)[13]), "=r"((r)[14]), "=r"((r)[15]),        \
          "=r"((r)[16]), "=r"((r)[17]), "=r"((r)[18]), "=r"((r)[19]),        \
          "=r"((r)[20]), "=r"((r)[21]), "=r"((r)[22]), "=r"((r)[23]),        \
          "=r"((r)[24]), "=r"((r)[25]), "=r"((r)[26]), "=r"((r)[27]),        \
          "=r"((r)[28]), "=r"((r)[29]), "=r"((r)[30]), "=r"((r)[31])         \
        : "r"(a))

// SW128 K-major descriptor base
#define DESCB ((2ULL << 61) | (1ULL << 46) | (64ULL << 32) | (1ULL << 16))
// idesc: F32 accum, BF16xBF16, N=256, M=128, cg1
#define IDESC 0x8400490u

// GEMM1: KC=32 stage = A(128x128B) + B(256x128B) = 48KB, 4 buffers
#define STG1 49152
#define B_OFF1 16384
// GEMM2: KC=32 stage = A(128x128B) + B(512x128B) = 80KB, 2 buffers
#define STG2 81920
#define B_OFF2 16384
#endif  // TC_PATH

#define SMEM_ALLOC (4 * 49152 + 1024)   // 197632 (covers gemm1 4x48K and gemm2 2x80K)

// fallback tiling constants
#define BK 32
#define AS_STR 36
#define BS_STR 136
#define A_STAGE (128 * AS_STR)
#define B_STAGE (BK * BS_STR)
#define NSTG 3

#if !TC_PATH
__device__ __forceinline__ void mma8(float* c, const uint32_t* a, const uint32_t* b) {
    asm volatile(
        "mma.sync.aligned.m16n8k8.row.col.f32.tf32.tf32.f32 "
        "{%0,%1,%2,%3},{%4,%5,%6,%7},{%8,%9},{%0,%1,%2,%3};"
        : "+f"(c[0]), "+f"(c[1]), "+f"(c[2]), "+f"(c[3])
        : "r"(a[0]), "r"(a[1]), "r"(a[2]), "r"(a[3]), "r"(b[0]), "r"(b[1]));
}
__device__ __forceinline__ void fb_load_stage(uint32_t smem_u32, int stg,
                                              const float* Ag, int ldA, int row0,
                                              int rows, const int* prow,
                                              const float* Bg, int ldB,
                                              int col0, int k0, int tid) {
    uint32_t as_b = smem_u32 + (uint32_t)stg * (A_STAGE * 4);
    uint32_t bs_b = smem_u32 + (uint32_t)(NSTG * A_STAGE + stg * B_STAGE) * 4;
#pragma unroll
    for (int i = 0; i < 4; i++) {
        int id = tid + 256 * i;
        int r = id >> 3, kc = (id & 7) * 4;
        int rr = (r < rows) ? r : rows - 1;
        int grow = prow ? prow[rr] : (row0 + rr);
        cpa16(as_b + (uint32_t)(r * AS_STR + kc) * 4,
              Ag + (size_t)grow * ldA + k0 + kc);
    }
#pragma unroll
    for (int i = 0; i < 4; i++) {
        int id = tid + 256 * i;
        int kr = id >> 5, nc = (id & 31) * 4;
        cpa16(bs_b + (uint32_t)(kr * BS_STR + nc) * 4,
              Bg + (size_t)(k0 + kr) * ldB + col0 + nc);
    }
}
__device__ __forceinline__ void fb_compute_stage(const uint32_t* smem, int stg,
                                                 int wm, int wn, int g, int t,
                                                 float c[2][8][4]) {
    const uint32_t* As = smem + stg * A_STAGE;
    const uint32_t* Bs = smem + NSTG * A_STAGE + stg * B_STAGE;
#pragma unroll
    for (int ks = 0; ks < BK; ks += 8) {
        uint32_t a[2][4], b[8][2];
#pragma unroll
        for (int mt = 0; mt < 2; mt++) {
            int m = wm * 32 + mt * 16 + g;
            a[mt][0] = As[m * AS_STR + ks + t];
            a[mt][1] = As[(m + 8) * AS_STR + ks + t];
            a[mt][2] = As[m * AS_STR + ks + t + 4];
            a[mt][3] = As[(m + 8) * AS_STR + ks + t + 4];
        }
#pragma unroll
        for (int nt = 0; nt < 8; nt++) {
            int n = wn * 64 + nt * 8 + g;
            b[nt][0] = Bs[(ks + t) * BS_STR + n];
            b[nt][1] = Bs[(ks + t + 4) * BS_STR + n];
        }
#pragma unroll
        for (int mt = 0; mt < 2; mt++)
#pragma unroll
            for (int nt = 0; nt < 8; nt++)
                mma8(c[mt][nt], a[mt], b[nt]);
    }
}
#endif  // !TC_PATH

// ---------------- 4: GEMM1 -----------------------------------------------------------
// grid (136, 2), 256 threads
__global__ __launch_bounds__(256) void k_gemm1(const float* __restrict__ b1) {
    extern __shared__ __align__(16) char dsm[];

#if TC_PATH
    if (blockIdx.y != 0) return;
    __shared__ uint32_t s_tslot;
    __shared__ __align__(8) uint64_t s_mbar[2];

    int e, row0, rows;
    if (!map_tile(blockIdx.x, e, row0, rows)) return;

    const int tid = threadIdx.x, wid = tid >> 5, lane = tid & 31;
    uint32_t sb = s2u(dsm);
    sb = (sb + 1023u) & ~1023u;
    const uint32_t mb0 = s2u(&s_mbar[0]);
    const uint32_t mb1 = s2u(&s_mbar[1]);
    const uint32_t tslot = s2u(&s_tslot);

    if (wid == 0) {
        asm volatile("tcgen05.alloc.cta_group::1.sync.aligned.shared::cta.b32 [%0], %1;"
                     :: "r"(tslot), "r"(256) : "memory");
        asm volatile("tcgen05.relinquish_alloc_permit.cta_group::1.sync.aligned;");
    }
    if (tid == 0) {
        asm volatile("mbarrier.init.shared.b64 [%0], 1;" :: "r"(mb0) : "memory");
        asm volatile("mbarrier.init.shared.b64 [%0], 1;" :: "r"(mb1) : "memory");
    }
    __syncthreads();
    uint32_t tb;
    asm volatile("ld.shared.b32 %0, [%1];" : "=r"(tb) : "r"(tslot));

    const int c = tid & 7;
    const int cq = (c & 3) * 8;
    const bool chi = (c < 4);
    const __nv_bfloat16* Asrc[4];
    uint32_t Adst[4];
#pragma unroll
    for (int i = 0; i < 4; i++) {
        int r = (tid >> 3) + 32 * i;
        int rr = (r < rows) ? r : rows - 1;
        int tok = g_perm[row0 + rr];
        Asrc[i] = (chi ? g_a_hi : g_a_lo) + (size_t)tok * DM + cq;
        Adst[i] = SWZ((uint32_t)(r * 128 + c * 16));
    }
    const __nv_bfloat16* Bbase = (chi ? g_w1_hi : g_w1_lo) + (size_t)e * HM * DM + cq;
    uint32_t Bdst[8];
#pragma unroll
    for (int i = 0; i < 8; i++) {
        int r = (tid >> 3) + 32 * i;
        Bdst[i] = B_OFF1 + SWZ((uint32_t)(r * 128 + c * 16));
    }

    auto load_stage = [&](int s) {
        uint32_t base = sb + (uint32_t)(s & 3) * STG1;
        int k0 = s * 32;
#pragma unroll
        for (int i = 0; i < 4; i++)
            cpa16(base + Adst[i], Asrc[i] + k0);
#pragma unroll
        for (int i = 0; i < 8; i++)
            cpa16(base + Bdst[i], Bbase + (size_t)((tid >> 3) + 32 * i) * DM + k0);
        cpa_commit();
    };

    const int S = DM / 32;  // 32
    load_stage(0);
    load_stage(1);
    uint32_t ph[2] = {0u, 0u};
    for (int s = 0; s < S; s++) {
        if (s >= 2) {
            uint32_t m = (s & 1) ? mb1 : mb0;
            mbar_wait(m, ph[s & 1]);
            ph[s & 1] ^= 1;
        }
        if (s + 2 < S) load_stage(s + 2);
        if (s + 2 < S) cpa_wait2();
        else if (s + 1 < S) cpa_wait1();
        else cpa_wait0();
        __syncthreads();
        if (wid == 0) {
            asm volatile("fence.proxy.async.shared::cta;" ::: "memory");
            if (elect_one()) {
                uint32_t b = sb + (uint32_t)(s & 3) * STG1;
                uint64_t ab = DESCB | ((uint64_t)(b >> 4) & 0x3FFF);
                uint64_t bb = DESCB | ((uint64_t)((b + B_OFF1) >> 4) & 0x3FFF);
#pragma unroll
                for (int ks = 0; ks < 2; ks++) {
                    uint64_t ah = ab + 2 * ks, al = ab + 4 + 2 * ks;
                    uint64_t bh = bb + 2 * ks, bl = bb + 4 + 2 * ks;
                    mma_ss_f16(tb, ah, bh, IDESC, (s == 0 && ks == 0) ? 0u : 1u);
                    mma_ss_f16(tb, ah, bl, IDESC, 1u);
                    mma_ss_f16(tb, al, bh, IDESC, 1u);
                }
                uint32_t m = (s & 1) ? mb1 : mb0;
                asm volatile(
                    "tcgen05.commit.cta_group::1.mbarrier::arrive::one.shared::cluster.b64 [%0];"
                    :: "r"(m) : "memory");
            }
        }
    }
    {
        uint32_t mA = (S & 1) ? mb1 : mb0;
        mbar_wait(mA, ph[S & 1]);
        ph[S & 1] ^= 1;
        uint32_t mBp = ((S - 1) & 1) ? mb1 : mb0;
        mbar_wait(mBp, ph[(S - 1) & 1]);
        ph[(S - 1) & 1] ^= 1;
    }
    asm volatile("tcgen05.fence::after_thread_sync;" ::: "memory");

    if (wid < 4) {
        int rl = wid * 32 + lane;
        bool ok = rl < rows;
        size_t hrow = (size_t)(row0 + rl) * HM;
        const float* bbp = b1 + e * HM;
#pragma unroll 1
        for (int cc = 0; cc < 8; cc++) {
            uint32_t r[32];
            LDTM32(r, tb + cc * 32);
            asm volatile("tcgen05.wait::ld.sync.aligned;" ::: "memory");
            if (ok) {
                uint32_t whi[16], wlo[16];
#pragma unroll
                for (int p = 0; p < 16; p++) {
                    float v0 = __uint_as_float(r[2 * p]) + __ldg(&bbp[cc * 32 + 2 * p]);
                    float v1 = __uint_as_float(r[2 * p + 1]) + __ldg(&bbp[cc * 32 + 2 * p + 1]);
                    v0 = 0.5f * v0 * (1.f + erff(v0 * 0.70710678118654752f));
                    v1 = 0.5f * v1 * (1.f + erff(v1 * 0.70710678118654752f));
                    __nv_bfloat16 h0, h1, l0, l1;
                    bfsplit(v0, h0, l0);
                    bfsplit(v1, h1, l1);
                    whi[p] = bfpack(h0, h1);
                    wlo[p] = bfpack(l0, l1);
                }
                uint4* dh = (uint4*)(g_h_hi + hrow + cc * 32);
                uint4* dl = (uint4*)(g_h_lo + hrow + cc * 32);
#pragma unroll
                for (int q = 0; q < 4; q++) {
                    dh[q] = make_uint4(whi[4 * q], whi[4 * q + 1], whi[4 * q + 2], whi[4 * q + 3]);
                    dl[q] = make_uint4(wlo[4 * q], wlo[4 * q + 1], wlo[4 * q + 2], wlo[4 * q + 3]);
                }
            }
        }
    }
    __syncthreads();
    if (wid == 0)
        asm volatile("tcgen05.dealloc.cta_group::1.sync.aligned.b32 %0, %1;"
                     :: "r"(tb), "r"(256));
#else
    uint32_t* smem = (uint32_t*)dsm;
    const uint32_t smem_u32 = s2u(dsm);

    int e, row0, rows;
    if (!map_tile(blockIdx.x, e, row0, rows)) return;
    const int col0 = blockIdx.y * 128;
    const int* prow = g_perm + row0;

    const float* Ag = g_xa;
    const float* Bg = g_w1t + (size_t)e * DM * HM;
    const int tid = threadIdx.x;
    const int w = tid >> 5, lane = tid & 31;
    const int wm = w >> 1, wn = w & 1;
    const int g = lane >> 2, t = lane & 3;

    float c[2][8][4];
#pragma unroll
    for (int i = 0; i < 2; i++)
#pragma unroll
        for (int j = 0; j < 8; j++)
#pragma unroll
            for (int q = 0; q < 4; q++) c[i][j][q] = 0.f;

    const int S = DM / BK;
    fb_load_stage(smem_u32, 0, Ag, DM, row0, rows, prow, Bg, HM, col0, 0, tid);
    cpa_commit();
    fb_load_stage(smem_u32, 1, Ag, DM, row0, rows, prow, Bg, HM, col0, BK, tid);
    cpa_commit();
    for (int s = 0; s < S; s++) {
        if (s + 1 < S) cpa_wait1(); else cpa_wait0();
        __syncthreads();
        if (s + 2 < S) {
            fb_load_stage(smem_u32, (s + 2) % NSTG, Ag, DM, row0, rows, prow, Bg, HM,
                          col0, (s + 2) * BK, tid);
            cpa_commit();
        }
        fb_compute_stage(smem, s % NSTG, wm, wn, g, t, c);
    }

#pragma unroll
    for (int mt = 0; mt < 2; mt++) {
        int rl0 = wm * 32 + mt * 16 + g;
#pragma unroll
        for (int half = 0; half < 2; half++) {
            int rl = rl0 + 8 * half;
            if (rl < rows) {
                size_t orow = (size_t)(row0 + rl) * HM;
#pragma unroll
                for (int nt = 0; nt < 8; nt++) {
                    int col = col0 + wn * 64 + nt * 8 + 2 * t;
                    float v0 = c[mt][nt][2 * half + 0] + __ldg(&b1[e * HM + col]);
                    float v1 = c[mt][nt][2 * half + 1] + __ldg(&b1[e * HM + col + 1]);
                    v0 = 0.5f * v0 * (1.f + erff(v0 * 0.70710678118654752f));
                    v1 = 0.5f * v1 * (1.f + erff(v1 * 0.70710678118654752f));
                    float2 o = make_float2(__uint_as_float(f2tf(v0)),
                                           __uint_as_float(f2tf(v1)));
                    *(float2*)&g_h[orow + col] = o;
                }
            }
        }
    }
#endif
}

// ---------------- 5: GEMM2 ------------------------------------------------------------
// grid (136, 8), 256 threads. tc path: by<2, 512 cols per CTA (two N=256 accumulators)
__global__ __launch_bounds__(256) void k_gemm2(const float* __restrict__ b2,
                                               float* __restrict__ out) {
    extern __shared__ __align__(16) char dsm[];

#if TC_PATH
    if (blockIdx.y >= 2) return;
    __shared__ uint32_t s_tslot;
    __shared__ __align__(8) uint64_t s_mbar[2];

    int e, row0, rows;
    if (!map_tile(blockIdx.x, e, row0, rows)) return;
    const int col0 = blockIdx.y * 512;

    const int tid = threadIdx.x, wid = tid >> 5, lane = tid & 31;
    uint32_t sb = s2u(dsm);
    sb = (sb + 1023u) & ~1023u;
    const uint32_t mb0 = s2u(&s_mbar[0]);
    const uint32_t mb1 = s2u(&s_mbar[1]);
    const uint32_t tslot = s2u(&s_tslot);

    if (wid == 0) {
        asm volatile("tcgen05.alloc.cta_group::1.sync.aligned.shared::cta.b32 [%0], %1;"
                     :: "r"(tslot), "r"(256) : "memory");
        asm volatile("tcgen05.relinquish_alloc_permit.cta_group::1.sync.aligned;");
    }
    if (tid == 0) {
        asm volatile("mbarrier.init.shared.b64 [%0], 1;" :: "r"(mb0) : "memory");
        asm volatile("mbarrier.init.shared.b64 [%0], 1;" :: "r"(mb1) : "memory");
    }
    __syncthreads();
    uint32_t tb;
    asm volatile("ld.shared.b32 %0, [%1];" : "=r"(tb) : "r"(tslot));

    const int c = tid & 7;
    const int cq = (c & 3) * 8;
    const bool chi = (c < 4);
    const __nv_bfloat16* Asrc[4];
    uint32_t Adst[4];
#pragma unroll
    for (int i = 0; i < 4; i++) {
        int r = (tid >> 3) + 32 * i;
        int rr = (r < rows) ? r : rows - 1;
        Asrc[i] = (chi ? g_h_hi : g_h_lo) + (size_t)(row0 + rr) * HM + cq;
        Adst[i] = SWZ((uint32_t)(r * 128 + c * 16));
    }
    const __nv_bfloat16* Bbase =
        (chi ? g_w2_hi : g_w2_lo) + (size_t)e * DM * HM + (size_t)col0 * HM + cq;
    uint32_t Bdst[16];
#pragma unroll
    for (int i = 0; i < 16; i++) {
        int r = (tid >> 3) + 32 * i;
        Bdst[i] = B_OFF2 + SWZ((uint32_t)(r * 128 + c * 16));
    }

    auto load_stage = [&](int s) {
        uint32_t base = sb + (uint32_t)(s & 1) * STG2;
        int k0 = s * 32;
#pragma unroll
        for (int i = 0; i < 4; i++)
            cpa16(base + Adst[i], Asrc[i] + k0);
#pragma unroll
        for (int i = 0; i < 16; i++)
            cpa16(base + Bdst[i], Bbase + (size_t)((tid >> 3) + 32 * i) * HM + k0);
        cpa_commit();
    };

    const int S = HM / 32;  // 8
    load_stage(0);
    load_stage(1);
    uint32_t ph[2] = {0u, 0u};
    for (int s = 0; s < S; s++) {
        if (s + 1 < S) cpa_wait1(); else cpa_wait0();
        __syncthreads();
        if (wid == 0) {
            asm volatile("fence.proxy.async.shared::cta;" ::: "memory");
            if (elect_one()) {
                uint32_t b = sb + (uint32_t)(s & 1) * STG2;
                uint64_t ab = DESCB | ((uint64_t)(b >> 4) & 0x3FFF);
                uint64_t b0 = DESCB | ((uint64_t)((b + B_OFF2) >> 4) & 0x3FFF);
                uint64_t b1d = DESCB | ((uint64_t)((b + B_OFF2 + 32768u) >> 4) & 0x3FFF);
#pragma unroll
                for (int ks = 0; ks < 2; ks++) {
                    uint64_t ah = ab + 2 * ks, al = ab + 4 + 2 * ks;
                    uint64_t bh0 = b0 + 2 * ks, bl0 = b0 + 4 + 2 * ks;
                    uint64_t bh1 = b1d + 2 * ks, bl1 = b1d + 4 + 2 * ks;
                    uint32_t en = (s == 0 && ks == 0) ? 0u : 1u;
                    mma_ss_f16(tb, ah, bh0, IDESC, en);
                    mma_ss_f16(tb, ah, bl0, IDESC, 1u);
                    mma_ss_f16(tb, al, bh0, IDESC, 1u);
                    mma_ss_f16(tb + 256, ah, bh1, IDESC, en);
                    mma_ss_f16(tb + 256, ah, bl1, IDESC, 1u);
                    mma_ss_f16(tb + 256, al, bh1, IDESC, 1u);
                }
                uint32_t m = (s & 1) ? mb1 : mb0;
                asm volatile(
                    "tcgen05.commit.cta_group::1.mbarrier::arrive::one.shared::cluster.b64 [%0];"
                    :: "r"(m) : "memory");
            }
        }
        if (s + 2 < S) {
            uint32_t m = (s & 1) ? mb1 : mb0;
            mbar_wait(m, ph[s & 1]);
            ph[s & 1] ^= 1;
            load_stage(s + 2);
        }
    }
    {
        uint32_t mA = ((S - 2) & 1) ? mb1 : mb0;
        mbar_wait(mA, ph[(S - 2) & 1]);
        ph[(S - 2) & 1] ^= 1;
        uint32_t mB = ((S - 1) & 1) ? mb1 : mb0;
        mbar_wait(mB, ph[(S - 1) & 1]);
        ph[(S - 1) & 1] ^= 1;
    }
    asm volatile("tcgen05.fence::after_thread_sync;" ::: "memory");

    if (wid < 4) {
        int rl = wid * 32 + lane;
        bool ok = rl < rows;
        int tok = ok ? g_perm[row0 + rl] : 0;
        float* orow = out + (size_t)tok * DM + col0;
        const float* bbp = b2 + e * DM + col0;
#pragma unroll 1
        for (int hc = 0; hc < 16; hc++) {
            int half = hc >> 3, cc = hc & 7;
            uint32_t r[32];
            LDTM32(r, tb + half * 256 + cc * 32);
            asm volatile("tcgen05.wait::ld.sync.aligned;" ::: "memory");
            if (ok) {
                int cb = half * 256 + cc * 32;
#pragma unroll
                for (int q = 0; q < 8; q++) {
                    float4 v;
                    v.x = __uint_as_float(r[4 * q + 0]) + __ldg(&bbp[cb + 4 * q + 0]);
                    v.y = __uint_as_float(r[4 * q + 1]) + __ldg(&bbp[cb + 4 * q + 1]);
                    v.z = __uint_as_float(r[4 * q + 2]) + __ldg(&bbp[cb + 4 * q + 2]);
                    v.w = __uint_as_float(r[4 * q + 3]) + __ldg(&bbp[cb + 4 * q + 3]);
                    ((float4*)(orow + cb))[q] = v;
                }
            }
        }
    }
    __syncthreads();
    if (wid == 0)
        asm volatile("tcgen05.dealloc.cta_group::1.sync.aligned.b32 %0, %1;"
                     :: "r"(tb), "r"(256));
#else
    uint32_t* smem = (uint32_t*)dsm;
    const uint32_t smem_u32 = s2u(dsm);

    int e, row0, rows;
    if (!map_tile(blockIdx.x, e, row0, rows)) return;
    const int col0 = blockIdx.y * 128;

    const float* Ag = g_h;
    const float* Bg = g_w2t + (size_t)e * HM * DM;
    const int tid = threadIdx.x;
    const int w = tid >> 5, lane = tid & 31;
    const int wm = w >> 1, wn = w & 1;
    const int g = lane >> 2, t = lane & 3;

    float c[2][8][4];
#pragma unroll
    for (int i = 0; i < 2; i++)
#pragma unroll
        for (int j = 0; j < 8; j++)
#pragma unroll
            for (int q = 0; q < 4; q++) c[i][j][q] = 0.f;

    const int S = HM / BK;
    fb_load_stage(smem_u32, 0, Ag, HM, row0, rows, nullptr, Bg, DM, col0, 0, tid);
    cpa_commit();
    fb_load_stage(smem_u32, 1, Ag, HM, row0, rows, nullptr, Bg, DM, col0, BK, tid);
    cpa_commit();
    for (int s = 0; s < S; s++) {
        if (s + 1 < S) cpa_wait1(); else cpa_wait0();
        __syncthreads();
        if (s + 2 < S) {
            fb_load_stage(smem_u32, (s + 2) % NSTG, Ag, HM, row0, rows, nullptr, Bg, DM,
                          col0, (s + 2) * BK, tid);
            cpa_commit();
        }
        fb_compute_stage(smem, s % NSTG, wm, wn, g, t, c);
    }

#pragma unroll
    for (int mt = 0; mt < 2; mt++) {
        int rl0 = wm * 32 + mt * 16 + g;
#pragma unroll
        for (int half = 0; half < 2; half++) {
            int rl = rl0 + 8 * half;
            if (rl < rows) {
                int tok = g_perm[row0 + rl];
                float* orow = out + (size_t)tok * DM;
#pragma unroll
                for (int nt = 0; nt < 8; nt++) {
                    int col = col0 + wn * 64 + nt * 8 + 2 * t;
                    float v0 = c[mt][nt][2 * half + 0] + __ldg(&b2[e * DM + col]);
                    float v1 = c[mt][nt][2 * half + 1] + __ldg(&b2[e * DM + col + 1]);
                    *(float2*)&orow[col] = make_float2(v0, v1);
                }
            }
        }
    }
#endif
}

// ---------------- launch -----------------------------------------------------------------
extern "C" void kernel_launch(void* const* d_in, const int* in_sizes, int n_in,
                              void* d_out, int out_size) {
    (void)in_sizes; (void)n_in; (void)out_size;
    const float* x  = (const float*)d_in[0];
    const float* Wg = (const float*)d_in[1];
    const float* ls = (const float*)d_in[2];
    const float* lb = (const float*)d_in[3];
    const float* W1 = (const float*)d_in[4];
    const float* b1 = (const float*)d_in[5];
    const float* W2 = (const float*)d_in[6];
    const float* b2 = (const float*)d_in[7];
    float* out = (float*)d_out;

    cudaFuncSetAttribute(k_gemm1, cudaFuncAttributeMaxDynamicSharedMemorySize, SMEM_ALLOC);
    cudaFuncSetAttribute(k_gemm2, cudaFuncAttributeMaxDynamicSharedMemorySize, SMEM_ALLOC);

    // second stream for weight prep (independent of routing); event fork/join so
    // it stays inside graph capture.
    static cudaStream_t s1 = nullptr;
    static cudaEvent_t ev_fork = nullptr, ev_join = nullptr;
    static bool stream_ok = false;
    static bool tried = false;
    if (!tried) {
        tried = true;
        if (cudaStreamCreateWithFlags(&s1, cudaStreamNonBlocking) == cudaSuccess &&
            cudaEventCreateWithFlags(&ev_fork, cudaEventDisableTiming) == cudaSuccess &&
            cudaEventCreateWithFlags(&ev_join, cudaEventDisableTiming) == cudaSuccess)
            stream_ok = true;
    }

    const int MAX_TILES = (N_TOK / 128) + EM;  // 136

    k_zero<<<1, 32>>>();
    if (stream_ok) {
        cudaEventRecord(ev_fork, 0);
        cudaStreamWaitEvent(s1, ev_fork, 0);
        k_wprep<<<dim3(512, EM), 256, 0, s1>>>(W1, W2);
        cudaEventRecord(ev_join, s1);
    }
    k_router<<<N_TOK / 8, 256>>>(x, Wg, ls, lb);
    k_perm<<<N_TOK / 256, 256>>>();
    if (stream_ok) {
        cudaStreamWaitEvent(0, ev_join, 0);
    } else {
        k_wprep<<<dim3(512, EM), 256>>>(W1, W2);
    }
    k_gemm1<<<dim3(MAX_TILES, 2), 256, SMEM_ALLOC>>>(b1);
    k_gemm2<<<dim3(MAX_TILES, 8), 256, SMEM_ALLOC>>>(b2, out);
}